// round 2
// baseline (speedup 1.0000x reference)
#include <cuda_runtime.h>
#include <cstdint>

#define B_SZ   4096
#define NB     64
#define DIM    256
#define N_WR   1001
#define N_ZQ   1000
#define CNT_E  1000
#define HID    512   // 2*DIM

// Scratch (device globals: allocation-free per harness rules)
static __device__ float g_wn[N_WR * DIM];     // normalized relation hyperplanes
static __device__ float g_zc[N_ZQ * HID];     // W1 @ zq[q] + attn_W_b, per q

// ---------------------------------------------------------------------------
// Kernel 1: normalize w_r rows. One warp per row.
// ---------------------------------------------------------------------------
__global__ void wn_kernel(const float* __restrict__ wr) {
    int r = blockIdx.x;
    int lane = threadIdx.x;
    const float4* row = (const float4*)(wr + r * DIM);
    float4 a = row[lane];
    float4 b = row[32 + lane];
    float ss = a.x*a.x + a.y*a.y + a.z*a.z + a.w*a.w
             + b.x*b.x + b.y*b.y + b.z*b.z + b.w*b.w;
#pragma unroll
    for (int off = 16; off; off >>= 1) ss += __shfl_xor_sync(0xffffffffu, ss, off);
    float nrm = fmaxf(sqrtf(ss), 1e-12f);
    float inv = 1.0f / nrm;
    float4* o = (float4*)(g_wn + r * DIM);
    float4 oa, ob;
    oa.x = a.x*inv; oa.y = a.y*inv; oa.z = a.z*inv; oa.w = a.w*inv;
    ob.x = b.x*inv; ob.y = b.y*inv; ob.z = b.z*inv; ob.w = b.w*inv;
    o[lane] = oa; o[32 + lane] = ob;
}

// ---------------------------------------------------------------------------
// Kernel 2: zc[q][o] = sum_k W[o][k]*zq[q][k] + bias[o]   (W1 = first 256 cols)
// Block handles 4 q values; warp handles o rows strided by 8.
// ---------------------------------------------------------------------------
__global__ void zc_kernel(const float* __restrict__ W,
                          const float* __restrict__ bias,
                          const float* __restrict__ zq) {
    __shared__ float zs[4][DIM];
    int q0 = blockIdx.x * 4;
    int tid = threadIdx.x;                 // 256 threads
#pragma unroll
    for (int qq = 0; qq < 4; ++qq) zs[qq][tid] = zq[(q0 + qq) * DIM + tid];
    __syncthreads();
    int warp = tid >> 5, lane = tid & 31;
    for (int o = warp; o < HID; o += 8) {
        const float4* Wrow = (const float4*)(W + (size_t)o * HID);  // cols 0..255 -> float4 0..63
        float4 w0 = Wrow[lane], w1 = Wrow[32 + lane];
        float p[4];
#pragma unroll
        for (int qq = 0; qq < 4; ++qq) {
            const float4* z4 = (const float4*)zs[qq];
            float4 z0 = z4[lane], z1 = z4[32 + lane];
            p[qq] = w0.x*z0.x + w0.y*z0.y + w0.z*z0.z + w0.w*z0.w
                  + w1.x*z1.x + w1.y*z1.y + w1.z*z1.z + w1.w*z1.w;
        }
#pragma unroll
        for (int off = 16; off; off >>= 1) {
#pragma unroll
            for (int qq = 0; qq < 4; ++qq)
                p[qq] += __shfl_xor_sync(0xffffffffu, p[qq], off);
        }
        if (lane == 0) {
            float bo = bias[o];
#pragma unroll
            for (int qq = 0; qq < 4; ++qq) g_zc[(q0 + qq) * HID + o] = p[qq] + bo;
        }
    }
}

// ---------------------------------------------------------------------------
// Main kernel: one CTA per batch element b, 256 threads.
// SMEM layout (floats):
//   E   [64][256]      e_tr rows                     0     .. 16384
//   Wt  [256][68]      W2 chunk, k-major, padded     16384 .. 33792
//   ZC  [512]                                         33792 .. 34304
//   UA  [512]                                         34304 .. 34816
//   RED [64][17]                                      34816 .. 35904
//   LG  [64]                                          35904 .. 35968
//   AT  [64]                                          35968 .. 36032
//   RI  [64] (int)                                    36032 .. 36096
// ---------------------------------------------------------------------------
#define SM_E    0
#define SM_W    16384
#define SM_ZC   33792
#define SM_UA   34304
#define SM_RED  34816
#define SM_LG   35904
#define SM_AT   35968
#define SM_RI   36032
#define SM_FLOATS 36096
#define SMEM_BYTES (SM_FLOATS * 4)

__global__ __launch_bounds__(256, 1)
void enc_attn_kernel(const int*   __restrict__ rid_g,
                     const float* __restrict__ e_g,
                     const float* __restrict__ rw_g,
                     const int*   __restrict__ qrid_g,
                     const float* __restrict__ W_g,     // attn_W_w [512][512]
                     const float* __restrict__ ua_g,    // u_a_w [512]
                     float*       __restrict__ out_g) {
    extern __shared__ float sm[];
    float* E  = sm + SM_E;
    float* Wt = sm + SM_W;
    float* ZC = sm + SM_ZC;
    float* UA = sm + SM_UA;
    float* RED = sm + SM_RED;
    float* LG = sm + SM_LG;
    float* AT = sm + SM_AT;
    int*   RI = (int*)(sm + SM_RI);

    int b = blockIdx.x;
    int tid = threadIdx.x;
    int warp = tid >> 5, lane = tid & 31;

    // ---- Phase A: TransH projection per neighbor, stored to SMEM ----
    for (int n = warp; n < NB; n += 8) {
        int r = rid_g[b * NB + n];
        const float4* er = (const float4*)(e_g + ((size_t)b * NB + n) * DIM);
        const float4* wp = (const float4*)(g_wn + r * DIM);
        float4 e0 = er[lane], e1 = er[32 + lane];
        float4 w0 = wp[lane], w1 = wp[32 + lane];
        float d = e0.x*w0.x + e0.y*w0.y + e0.z*w0.z + e0.w*w0.w
                + e1.x*w1.x + e1.y*w1.y + e1.z*w1.z + e1.w*w1.w;
#pragma unroll
        for (int off = 16; off; off >>= 1) d += __shfl_xor_sync(0xffffffffu, d, off);
        float mask = (r < CNT_E) ? 1.0f : 0.0f;
        float4 t0, t1;
        t0.x = (e0.x - d*w0.x)*mask; t0.y = (e0.y - d*w0.y)*mask;
        t0.z = (e0.z - d*w0.z)*mask; t0.w = (e0.w - d*w0.w)*mask;
        t1.x = (e1.x - d*w1.x)*mask; t1.y = (e1.y - d*w1.y)*mask;
        t1.z = (e1.z - d*w1.z)*mask; t1.w = (e1.w - d*w1.w)*mask;
        ((float4*)E)[n * 64 + lane]      = t0;
        ((float4*)E)[n * 64 + 32 + lane] = t1;
        if (lane == 0) RI[n] = r;
    }
    // zc (per-batch constant vector) + u_a into SMEM
    int q = qrid_g[b];
    for (int i = tid; i < HID; i += 256) {
        ZC[i] = g_zc[q * HID + i];
        UA[i] = ua_g[i];
    }

    // ---- Phase B: logits via tiled GEMM  v[n][o] = W2[o]·e_tr[n] + zc[o] ----
    int tx = tid & 15, ty = tid >> 4;      // 16x16 threads; thread tile 4n x 4o
    int n0 = ty * 4;
    float plog[4] = {0.f, 0.f, 0.f, 0.f};
    const float4* E4 = (const float4*)E;

    for (int oc = 0; oc < 8; ++oc) {
        __syncthreads();
        // stage W2 chunk transposed: Wt[k][o_local], k-row stride 68 floats
        for (int idx = tid; idx < 64 * 256; idx += 256) {
            int o = idx >> 8, k = idx & 255;
            Wt[k * 68 + o] = W_g[(size_t)(oc * 64 + o) * HID + DIM + k];
        }
        __syncthreads();

        float v[4][4] = {};
        const float4* W4 = (const float4*)Wt;     // row stride 17 float4
#pragma unroll 4
        for (int kk = 0; kk < 64; ++kk) {
            float4 a0 = E4[(n0 + 0) * 64 + kk];
            float4 a1 = E4[(n0 + 1) * 64 + kk];
            float4 a2 = E4[(n0 + 2) * 64 + kk];
            float4 a3 = E4[(n0 + 3) * 64 + kk];
            const float* p0 = (const float*)&a0;
            const float* p1 = (const float*)&a1;
            const float* p2 = (const float*)&a2;
            const float* p3 = (const float*)&a3;
#pragma unroll
            for (int s = 0; s < 4; ++s) {
                float4 wv = W4[(kk * 4 + s) * 17 + tx];
                float x0 = p0[s], x1 = p1[s], x2 = p2[s], x3 = p3[s];
                v[0][0] += x0*wv.x; v[0][1] += x0*wv.y; v[0][2] += x0*wv.z; v[0][3] += x0*wv.w;
                v[1][0] += x1*wv.x; v[1][1] += x1*wv.y; v[1][2] += x1*wv.z; v[1][3] += x1*wv.w;
                v[2][0] += x2*wv.x; v[2][1] += x2*wv.y; v[2][2] += x2*wv.z; v[2][3] += x2*wv.w;
                v[3][0] += x3*wv.x; v[3][1] += x3*wv.y; v[3][2] += x3*wv.z; v[3][3] += x3*wv.w;
            }
        }
#pragma unroll
        for (int j = 0; j < 4; ++j) {
            int o = oc * 64 + tx * 4 + j;
            float c = ZC[o], ua = UA[o];
#pragma unroll
            for (int i = 0; i < 4; ++i) {
                float h = tanhf(v[i][j] + c);
                plog[i] += ua * h;
            }
        }
    }
    // cross-thread logit reduction (16 partials per n)
#pragma unroll
    for (int i = 0; i < 4; ++i) RED[(n0 + i) * 17 + tx] = plog[i];
    __syncthreads();
    if (tid < 64) {
        float s = 0.f;
#pragma unroll
        for (int j = 0; j < 16; ++j) s += RED[tid * 17 + j];
        if (RI[tid] == CNT_E) s -= 1e19f;
        LG[tid] = s;
    }
    __syncthreads();

    // ---- Phase C: softmax + rw (warp 0) ----
    if (tid < 32) {
        float x0 = LG[tid], x1 = LG[tid + 32];
        float m = fmaxf(x0, x1);
#pragma unroll
        for (int off = 16; off; off >>= 1) m = fmaxf(m, __shfl_xor_sync(0xffffffffu, m, off));
        float ex0 = expf(x0 - m), ex1 = expf(x1 - m);
        float s = ex0 + ex1;
#pragma unroll
        for (int off = 16; off; off >>= 1) s += __shfl_xor_sync(0xffffffffu, s, off);
        float inv = 1.0f / s;
        AT[tid]      = ex0 * inv + rw_g[b * NB + tid];
        AT[tid + 32] = ex1 * inv + rw_g[b * NB + tid + 32];
    }
    __syncthreads();

    // ---- Phase D: out[d] = sum_n attn[n] * e_tr[n][d] ----
    float acc = 0.f;
#pragma unroll 8
    for (int n = 0; n < NB; ++n) acc += AT[n] * E[n * 256 + tid];
    out_g[(size_t)b * DIM + tid] = acc;
}

// ---------------------------------------------------------------------------
extern "C" void kernel_launch(void* const* d_in, const int* in_sizes, int n_in,
                              void* d_out, int out_size) {
    const int*   rid  = (const int*)d_in[0];
    const float* e    = (const float*)d_in[1];
    const float* rw   = (const float*)d_in[2];
    const int*   qrid = (const int*)d_in[3];
    const float* wr   = (const float*)d_in[4];
    const float* zq   = (const float*)d_in[5];
    const float* W    = (const float*)d_in[6];
    const float* Wb   = (const float*)d_in[7];
    const float* ua   = (const float*)d_in[8];
    // d_in[9] = u_a_b: additive constant, softmax-invariant -> unused
    float* out = (float*)d_out;

    static bool attr_set = false;
    if (!attr_set) {
        cudaFuncSetAttribute(enc_attn_kernel,
                             cudaFuncAttributeMaxDynamicSharedMemorySize, SMEM_BYTES);
        attr_set = true;
    }

    wn_kernel<<<N_WR, 32>>>(wr);
    zc_kernel<<<N_ZQ / 4, 256>>>(W, Wb, zq);
    enc_attn_kernel<<<B_SZ, 256, SMEM_BYTES>>>(rid, e, rw, qrid, W, ua, out);
}

// round 5
// speedup vs baseline: 5.1997x; 5.1997x over previous
#include <cuda_runtime.h>
#include <cuda_bf16.h>
#include <cstdint>

#define B_SZ   4096
#define NB     64
#define DIM    256
#define N_WR   1001
#define N_ZQ   1000
#define CNT_E  1000
#define HID    512

// -------- device globals (scratch; allocation-free per harness rules) -------
static __device__ float g_wn[N_WR * DIM];            // normalized hyperplanes
static __device__ float g_zc[N_ZQ * HID];            // W1@zq + b
static __device__ __nv_bfloat16 g_w2[HID * DIM];     // W2 bf16 [o][k] row-major

// ---------------------------------------------------------------------------
// helpers
// ---------------------------------------------------------------------------
__device__ __forceinline__ uint32_t smem_u32(const void* p) {
    uint32_t a;
    asm("{ .reg .u64 t; cvta.to.shared.u64 t, %1; cvt.u32.u64 %0, t; }" : "=r"(a) : "l"(p));
    return a;
}
__device__ __forceinline__ float tanh_fast(float x) {
    float y; asm("tanh.approx.f32 %0, %1;" : "=f"(y) : "f"(x)); return y;
}

#define LDSM4(r, addr)                                                        \
    asm volatile("ldmatrix.sync.aligned.m8n8.x4.shared.b16 {%0,%1,%2,%3}, [%4];" \
        : "=r"((r)[0]), "=r"((r)[1]), "=r"((r)[2]), "=r"((r)[3]) : "r"(addr))

#define MMA16816(d, a, b0, b1)                                                \
    asm volatile("mma.sync.aligned.m16n8k16.row.col.f32.bf16.bf16.f32 "       \
        "{%0,%1,%2,%3}, {%4,%5,%6,%7}, {%8,%9}, {%0,%1,%2,%3};"               \
        : "+f"((d)[0]), "+f"((d)[1]), "+f"((d)[2]), "+f"((d)[3])              \
        : "r"((a)[0]), "r"((a)[1]), "r"((a)[2]), "r"((a)[3]), "r"(b0), "r"(b1))

#define CP_ASYNC16(dst, src) \
    asm volatile("cp.async.cg.shared.global [%0], [%1], 16;" :: "r"(dst), "l"(src))
#define CP_COMMIT()  asm volatile("cp.async.commit_group;" ::: "memory")
#define CP_WAIT0()   asm volatile("cp.async.wait_group 0;" ::: "memory")
#define CP_WAIT1()   asm volatile("cp.async.wait_group 1;" ::: "memory")

// ---------------------------------------------------------------------------
// Prep kernel 1: normalize w_r rows (one warp per row)
// ---------------------------------------------------------------------------
__global__ void wn_kernel(const float* __restrict__ wr) {
    int r = blockIdx.x, lane = threadIdx.x;
    const float4* row = (const float4*)(wr + r * DIM);
    float4 a = row[lane], b = row[32 + lane];
    float ss = a.x*a.x + a.y*a.y + a.z*a.z + a.w*a.w
             + b.x*b.x + b.y*b.y + b.z*b.z + b.w*b.w;
#pragma unroll
    for (int o = 16; o; o >>= 1) ss += __shfl_xor_sync(~0u, ss, o);
    float inv = 1.0f / fmaxf(sqrtf(ss), 1e-12f);
    float4* out = (float4*)(g_wn + r * DIM);
    float4 oa = {a.x*inv, a.y*inv, a.z*inv, a.w*inv};
    float4 ob = {b.x*inv, b.y*inv, b.z*inv, b.w*inv};
    out[lane] = oa; out[32 + lane] = ob;
}

// ---------------------------------------------------------------------------
// Prep kernel 2: zc[q][o] = W1[o]·zq[q] + bias[o]
// ---------------------------------------------------------------------------
__global__ void zc_kernel(const float* __restrict__ W, const float* __restrict__ bias,
                          const float* __restrict__ zq) {
    __shared__ float zs[4][DIM];
    int q0 = blockIdx.x * 4, tid = threadIdx.x;
#pragma unroll
    for (int qq = 0; qq < 4; ++qq) zs[qq][tid] = zq[(q0 + qq) * DIM + tid];
    __syncthreads();
    int warp = tid >> 5, lane = tid & 31;
    for (int o = warp; o < HID; o += 8) {
        const float4* Wr = (const float4*)(W + (size_t)o * HID);
        float4 w0 = Wr[lane], w1 = Wr[32 + lane];
        float p[4];
#pragma unroll
        for (int qq = 0; qq < 4; ++qq) {
            const float4* z4 = (const float4*)zs[qq];
            float4 z0 = z4[lane], z1 = z4[32 + lane];
            p[qq] = w0.x*z0.x + w0.y*z0.y + w0.z*z0.z + w0.w*z0.w
                  + w1.x*z1.x + w1.y*z1.y + w1.z*z1.z + w1.w*z1.w;
        }
#pragma unroll
        for (int off = 16; off; off >>= 1)
#pragma unroll
            for (int qq = 0; qq < 4; ++qq) p[qq] += __shfl_xor_sync(~0u, p[qq], off);
        if (lane == 0) {
            float bo = bias[o];
#pragma unroll
            for (int qq = 0; qq < 4; ++qq) g_zc[(q0 + qq) * HID + o] = p[qq] + bo;
        }
    }
}

// ---------------------------------------------------------------------------
// Prep kernel 3: pack W2 (cols 256..511 of attn_W_w) -> bf16 row-major [o][k]
// ---------------------------------------------------------------------------
__global__ void w2pack_kernel(const float* __restrict__ W) {
    int o = blockIdx.x, k = threadIdx.x;
    g_w2[o * DIM + k] = __float2bfloat16(W[(size_t)o * HID + DIM + k]);
}

// ---------------------------------------------------------------------------
// Main kernel: one CTA per 2 batches, 256 threads (8 warps).
// SMEM (bytes):
//   EA   [128 rows][264 bf16]  (stride 528B)   0      .. 67584
//   B0   [128][264 bf16]                       67584  .. 135168
//   B1   [128][264 bf16]                       135168 .. 202752
//   ZC   2*512 f32      202752   UA 512 f32    206848
//   DV 208896  RID 209408  LG 209920  AT 210432  CA 210944  CB 211456
//   PART [128][2] f32   211968 .. 212992
// ---------------------------------------------------------------------------
#define RSTRIDE   528      // 264 bf16
#define OFF_EA    0
#define OFF_B0    67584
#define OFF_B1    135168
#define OFF_ZC    202752
#define OFF_UA    206848
#define OFF_DV    208896
#define OFF_RID   209408
#define OFF_LG    209920
#define OFF_AT    210432
#define OFF_CA    210944
#define OFF_CB    211456
#define OFF_PART  211968
#define SMEM_BYTES 212992

__global__ __launch_bounds__(256, 1)
void enc_attn_kernel(const int*   __restrict__ rid_g,
                     const float* __restrict__ e_g,
                     const float* __restrict__ rw_g,
                     const int*   __restrict__ qrid_g,
                     const float* __restrict__ ua_g,
                     float*       __restrict__ out_g) {
    extern __shared__ char sm[];
    uint32_t smb = smem_u32(sm);

    float* ZC  = (float*)(sm + OFF_ZC);
    float* UA  = (float*)(sm + OFF_UA);
    float* DV  = (float*)(sm + OFF_DV);
    int*   RID = (int*)  (sm + OFF_RID);
    float* LG  = (float*)(sm + OFF_LG);
    float* AT  = (float*)(sm + OFF_AT);
    float* CA  = (float*)(sm + OFF_CA);
    float* CB  = (float*)(sm + OFF_CB);
    float* PART= (float*)(sm + OFF_PART);

    int tid = threadIdx.x, w = tid >> 5, lane = tid & 31;
    int b0 = blockIdx.x * 2;

    // ---- stage W2 chunk 0 early (cp.async overlaps Phase A's gmem loads) ----
    {
        const char* srcb = (const char*)g_w2;   // chunk 0: rows 0..127
#pragma unroll
        for (int i = 0; i < 16; ++i) {
            int g = tid + i * 256;              // 4096 granules of 16B
            int r = g >> 5, gc = g & 31;
            CP_ASYNC16(smb + OFF_B0 + r * RSTRIDE + gc * 16,
                       srcb + r * 512 + gc * 16);
        }
        CP_COMMIT();
    }

    // ---- Phase A: TransH projection -> bf16 SMEM rows; save d, rid ----
    for (int row = w; row < 128; row += 8) {
        int gb = b0 + (row >> 6);
        int n  = row & 63;
        int r  = rid_g[gb * NB + n];
        const float4* er = (const float4*)(e_g + ((size_t)gb * NB + n) * DIM);
        const float4* wp = (const float4*)(g_wn + (size_t)r * DIM);
        float4 e0 = er[2*lane], e1 = er[2*lane+1];
        float4 w0 = wp[2*lane], w1 = wp[2*lane+1];
        float d = e0.x*w0.x + e0.y*w0.y + e0.z*w0.z + e0.w*w0.w
                + e1.x*w1.x + e1.y*w1.y + e1.z*w1.z + e1.w*w1.w;
#pragma unroll
        for (int o = 16; o; o >>= 1) d += __shfl_xor_sync(~0u, d, o);
        float m = (r < CNT_E) ? 1.0f : 0.0f;
        __nv_bfloat162 p0 = __floats2bfloat162_rn((e0.x - d*w0.x)*m, (e0.y - d*w0.y)*m);
        __nv_bfloat162 p1 = __floats2bfloat162_rn((e0.z - d*w0.z)*m, (e0.w - d*w0.w)*m);
        __nv_bfloat162 p2 = __floats2bfloat162_rn((e1.x - d*w1.x)*m, (e1.y - d*w1.y)*m);
        __nv_bfloat162 p3 = __floats2bfloat162_rn((e1.z - d*w1.z)*m, (e1.w - d*w1.w)*m);
        uint4 pk;
        pk.x = *(uint32_t*)&p0; pk.y = *(uint32_t*)&p1;
        pk.z = *(uint32_t*)&p2; pk.w = *(uint32_t*)&p3;
        *(uint4*)(sm + OFF_EA + row * RSTRIDE + lane * 16) = pk;
        if (lane == 0) { DV[row] = d; RID[row] = r; }
    }
    {
        int q0 = qrid_g[b0], q1 = qrid_g[b0 + 1];
        for (int o = tid; o < HID; o += 256) {
            ZC[o]       = g_zc[(size_t)q0 * HID + o];
            ZC[512 + o] = g_zc[(size_t)q1 * HID + o];
            UA[o]       = ua_g[o];
        }
    }
    __syncthreads();

    // ---- Phase B: 4 N-chunks of 128 cols; cp.async double-buffered W2 ----
    int mw = w & 3, nw = w >> 2;
    int m0 = mw * 32, n0 = nw * 64;

    // ldmatrix lane addresses (fixed per thread)
    uint32_t rowA0 = smb + OFF_EA + (m0 + (lane & 15)) * RSTRIDE + (lane >> 4) * 16;
    uint32_t rowA1 = rowA0 + 16 * RSTRIDE;
    uint32_t rbOff[4];
#pragma unroll
    for (int j = 0; j < 4; ++j)
        rbOff[j] = (uint32_t)((n0 + j * 16 + (lane & 7) + ((lane >> 4) << 3)) * RSTRIDE
                              + ((lane >> 3) & 1) * 16);

    const float* zcb = ZC + (m0 >> 6) * 512;   // batch-local zc
    float p[4] = {0.f, 0.f, 0.f, 0.f};         // per-lane logit partials

#pragma unroll 1
    for (int c = 0; c < 4; ++c) {
        if (c < 3) {   // prefetch next chunk
            const char* srcb = (const char*)g_w2 + (size_t)(c + 1) * 128 * 512;
            uint32_t dstb = smb + (((c + 1) & 1) ? OFF_B1 : OFF_B0);
#pragma unroll
            for (int i = 0; i < 16; ++i) {
                int g = tid + i * 256;
                int r = g >> 5, gc = g & 31;
                CP_ASYNC16(dstb + r * RSTRIDE + gc * 16, srcb + r * 512 + gc * 16);
            }
            CP_COMMIT();
            CP_WAIT1();
        } else {
            CP_WAIT0();
        }
        __syncthreads();                        // current chunk visible to all

        uint32_t bBase = smb + ((c & 1) ? OFF_B1 : OFF_B0);
        float acc[2][8][4];
#pragma unroll
        for (int im = 0; im < 2; ++im)
#pragma unroll
            for (int jn = 0; jn < 8; ++jn)
#pragma unroll
                for (int e = 0; e < 4; ++e) acc[im][jn][e] = 0.f;

#pragma unroll
        for (int ks = 0; ks < 16; ++ks) {
            uint32_t kb = ks * 32;
            uint32_t a0[4], a1[4], bfr[4][4];
            LDSM4(a0, rowA0 + kb);
            LDSM4(a1, rowA1 + kb);
#pragma unroll
            for (int j = 0; j < 4; ++j) LDSM4(bfr[j], bBase + rbOff[j] + kb);
#pragma unroll
            for (int jn = 0; jn < 8; ++jn) {
                uint32_t bb0 = bfr[jn >> 1][(jn & 1) * 2];
                uint32_t bb1 = bfr[jn >> 1][(jn & 1) * 2 + 1];
                MMA16816(acc[0][jn], a0, bb0, bb1);
                MMA16816(acc[1][jn], a1, bb0, bb1);
            }
        }

        // fused epilogue on fragments: logit partial += ua * tanh(v + zc)
        int cbase = c * 128 + n0 + (lane & 3) * 2;
#pragma unroll
        for (int im = 0; im < 2; ++im)
#pragma unroll
            for (int jn = 0; jn < 8; ++jn) {
                int col0 = cbase + jn * 8;
#pragma unroll
                for (int e = 0; e < 4; ++e) {
                    int col = col0 + (e & 1);
                    float h = tanh_fast(acc[im][jn][e] + zcb[col]);
                    p[im * 2 + (e >> 1)] = fmaf(UA[col], h, p[im * 2 + (e >> 1)]);
                }
            }
        __syncthreads();                        // done reading buffer before restage
    }

    // ---- reduce partials across the 4 lanes of each row group ----
#pragma unroll
    for (int o = 1; o <= 2; o <<= 1)
#pragma unroll
        for (int k = 0; k < 4; ++k) p[k] += __shfl_xor_sync(~0u, p[k], o);
    if ((lane & 3) == 0) {
#pragma unroll
        for (int k = 0; k < 4; ++k) {
            int row = m0 + (k >> 1) * 16 + (k & 1) * 8 + (lane >> 2);
            PART[row * 2 + nw] = p[k];
        }
    }
    __syncthreads();

    if (tid < 128) {
        float s = PART[tid * 2] + PART[tid * 2 + 1];
        if (RID[tid] == CNT_E) s -= 1e19f;
        LG[tid] = s;
    }
    __syncthreads();

    // ---- softmax + rw (warp i handles batch i) ----
    if (w < 2) {
        int base = w * 64;
        float x0 = LG[base + lane], x1 = LG[base + 32 + lane];
        float mx = fmaxf(x0, x1);
#pragma unroll
        for (int o = 16; o; o >>= 1) mx = fmaxf(mx, __shfl_xor_sync(~0u, mx, o));
        float ex0 = expf(x0 - mx), ex1 = expf(x1 - mx);
        float s = ex0 + ex1;
#pragma unroll
        for (int o = 16; o; o >>= 1) s += __shfl_xor_sync(~0u, s, o);
        float inv = 1.0f / s;
        AT[base + lane]      = ex0 * inv + rw_g[(b0 + w) * NB + lane];
        AT[base + 32 + lane] = ex1 * inv + rw_g[(b0 + w) * NB + 32 + lane];
    }
    __syncthreads();
    if (tid < 128) {
        int r = RID[tid];
        float m = (r < CNT_E) ? 1.0f : 0.0f;
        float a = AT[tid] * m;
        CA[tid] = a;
        CB[tid] = a * DV[tid];
    }
    __syncthreads();

    // ---- Phase D: out = sum_n CA*e - CB*wn  (full fp32 path) ----
#pragma unroll 1
    for (int i = 0; i < 2; ++i) {
        int gb = b0 + i;
        const float* eb = e_g + (size_t)gb * NB * DIM + tid;
        float acc = 0.0f;
#pragma unroll 8
        for (int n = 0; n < 64; ++n) {
            float ca = CA[i * 64 + n], cb = CB[i * 64 + n];
            acc += ca * eb[n * DIM] - cb * g_wn[(size_t)RID[i * 64 + n] * DIM + tid];
        }
        out_g[(size_t)gb * DIM + tid] = acc;
    }
}

// ---------------------------------------------------------------------------
extern "C" void kernel_launch(void* const* d_in, const int* in_sizes, int n_in,
                              void* d_out, int out_size) {
    const int*   rid  = (const int*)d_in[0];
    const float* e    = (const float*)d_in[1];
    const float* rw   = (const float*)d_in[2];
    const int*   qrid = (const int*)d_in[3];
    const float* wr   = (const float*)d_in[4];
    const float* zq   = (const float*)d_in[5];
    const float* W    = (const float*)d_in[6];
    const float* Wb   = (const float*)d_in[7];
    const float* ua   = (const float*)d_in[8];
    float* out = (float*)d_out;

    static bool attr_set = false;
    if (!attr_set) {
        cudaFuncSetAttribute(enc_attn_kernel,
                             cudaFuncAttributeMaxDynamicSharedMemorySize, SMEM_BYTES);
        attr_set = true;
    }

    wn_kernel<<<N_WR, 32>>>(wr);
    zc_kernel<<<N_ZQ / 4, 256>>>(W, Wb, zq);
    w2pack_kernel<<<HID, DIM>>>(W);
    enc_attn_kernel<<<B_SZ / 2, 256, SMEM_BYTES>>>(rid, e, rw, qrid, ua, out);
}

// round 6
// speedup vs baseline: 6.0680x; 1.1670x over previous
#include <cuda_runtime.h>
#include <cuda_bf16.h>
#include <cstdint>

#define B_SZ   4096
#define NB     64
#define DIM    256
#define N_WR   1001
#define N_ZQ   1000
#define CNT_E  1000
#define HID    512

// -------- device globals (scratch; allocation-free per harness rules) -------
static __device__ float g_wn[N_WR * DIM];            // normalized hyperplanes
static __device__ float g_zc[N_ZQ * HID];            // W1@zq + b
static __device__ __nv_bfloat16 g_w2[HID * DIM];     // W2 bf16 [o][k] row-major

// ---------------------------------------------------------------------------
// helpers
// ---------------------------------------------------------------------------
__device__ __forceinline__ uint32_t smem_u32(const void* p) {
    uint32_t a;
    asm("{ .reg .u64 t; cvta.to.shared.u64 t, %1; cvt.u32.u64 %0, t; }" : "=r"(a) : "l"(p));
    return a;
}
__device__ __forceinline__ float tanh_fast(float x) {
    float y; asm("tanh.approx.f32 %0, %1;" : "=f"(y) : "f"(x)); return y;
}

#define LDSM4(r, addr)                                                        \
    asm volatile("ldmatrix.sync.aligned.m8n8.x4.shared.b16 {%0,%1,%2,%3}, [%4];" \
        : "=r"((r)[0]), "=r"((r)[1]), "=r"((r)[2]), "=r"((r)[3]) : "r"(addr))

#define MMA16816(d, a, b0, b1)                                                \
    asm volatile("mma.sync.aligned.m16n8k16.row.col.f32.bf16.bf16.f32 "       \
        "{%0,%1,%2,%3}, {%4,%5,%6,%7}, {%8,%9}, {%0,%1,%2,%3};"               \
        : "+f"((d)[0]), "+f"((d)[1]), "+f"((d)[2]), "+f"((d)[3])              \
        : "r"((a)[0]), "r"((a)[1]), "r"((a)[2]), "r"((a)[3]), "r"(b0), "r"(b1))

#define CP_ASYNC16(dst, src) \
    asm volatile("cp.async.cg.shared.global [%0], [%1], 16;" :: "r"(dst), "l"(src))
#define CP_COMMIT()  asm volatile("cp.async.commit_group;" ::: "memory")
#define CP_WAIT0()   asm volatile("cp.async.wait_group 0;" ::: "memory")
#define CP_WAIT1()   asm volatile("cp.async.wait_group 1;" ::: "memory")

// ---------------------------------------------------------------------------
// Prep kernel 1: normalize w_r rows (one warp per row)
// ---------------------------------------------------------------------------
__global__ void wn_kernel(const float* __restrict__ wr) {
    int r = blockIdx.x, lane = threadIdx.x;
    const float4* row = (const float4*)(wr + r * DIM);
    float4 a = row[lane], b = row[32 + lane];
    float ss = a.x*a.x + a.y*a.y + a.z*a.z + a.w*a.w
             + b.x*b.x + b.y*b.y + b.z*b.z + b.w*b.w;
#pragma unroll
    for (int o = 16; o; o >>= 1) ss += __shfl_xor_sync(~0u, ss, o);
    float inv = 1.0f / fmaxf(sqrtf(ss), 1e-12f);
    float4* out = (float4*)(g_wn + r * DIM);
    float4 oa = {a.x*inv, a.y*inv, a.z*inv, a.w*inv};
    float4 ob = {b.x*inv, b.y*inv, b.z*inv, b.w*inv};
    out[lane] = oa; out[32 + lane] = ob;
}

// ---------------------------------------------------------------------------
// Prep kernel 2: zc[q][o] = W1[o]·zq[q] + bias[o]
// ---------------------------------------------------------------------------
__global__ void zc_kernel(const float* __restrict__ W, const float* __restrict__ bias,
                          const float* __restrict__ zq) {
    __shared__ float zs[4][DIM];
    int q0 = blockIdx.x * 4, tid = threadIdx.x;
#pragma unroll
    for (int qq = 0; qq < 4; ++qq) zs[qq][tid] = zq[(q0 + qq) * DIM + tid];
    __syncthreads();
    int warp = tid >> 5, lane = tid & 31;
    for (int o = warp; o < HID; o += 8) {
        const float4* Wr = (const float4*)(W + (size_t)o * HID);
        float4 w0 = Wr[lane], w1 = Wr[32 + lane];
        float p[4];
#pragma unroll
        for (int qq = 0; qq < 4; ++qq) {
            const float4* z4 = (const float4*)zs[qq];
            float4 z0 = z4[lane], z1 = z4[32 + lane];
            p[qq] = w0.x*z0.x + w0.y*z0.y + w0.z*z0.z + w0.w*z0.w
                  + w1.x*z1.x + w1.y*z1.y + w1.z*z1.z + w1.w*z1.w;
        }
#pragma unroll
        for (int off = 16; off; off >>= 1)
#pragma unroll
            for (int qq = 0; qq < 4; ++qq) p[qq] += __shfl_xor_sync(~0u, p[qq], off);
        if (lane == 0) {
            float bo = bias[o];
#pragma unroll
            for (int qq = 0; qq < 4; ++qq) g_zc[(q0 + qq) * HID + o] = p[qq] + bo;
        }
    }
}

// ---------------------------------------------------------------------------
// Prep kernel 3: pack W2 (cols 256..511 of attn_W_w) -> bf16 row-major [o][k]
// ---------------------------------------------------------------------------
__global__ void w2pack_kernel(const float* __restrict__ W) {
    int o = blockIdx.x, k = threadIdx.x;
    g_w2[o * DIM + k] = __float2bfloat16(W[(size_t)o * HID + DIM + k]);
}

// ---------------------------------------------------------------------------
// Main kernel: one CTA per 2 batches, 512 threads (16 warps, 4m x 4n).
// SMEM (bytes):
//   EA   [128 rows][264 bf16]  (stride 528B)   0      .. 67584
//   B0   [128][264 bf16]                       67584  .. 135168
//   B1   [128][264 bf16]                       135168 .. 202752
//   ZC 202752 (2*512 f32)  UA 206848 (512 f32)
//   DV 208896  RID 209408  LG 209920  AT 210432  CA 210944  CB 211456
//   PART [128][4] f32   211968 .. 214016
// ---------------------------------------------------------------------------
#define RSTRIDE   528
#define OFF_EA    0
#define OFF_B0    67584
#define OFF_B1    135168
#define OFF_ZC    202752
#define OFF_UA    206848
#define OFF_DV    208896
#define OFF_RID   209408
#define OFF_LG    209920
#define OFF_AT    210432
#define OFF_CA    210944
#define OFF_CB    211456
#define OFF_PART  211968
#define SMEM_BYTES 214016

#define NT 512

__global__ __launch_bounds__(NT, 1)
void enc_attn_kernel(const int*   __restrict__ rid_g,
                     const float* __restrict__ e_g,
                     const float* __restrict__ rw_g,
                     const int*   __restrict__ qrid_g,
                     const float* __restrict__ ua_g,
                     float*       __restrict__ out_g) {
    extern __shared__ char sm[];
    uint32_t smb = smem_u32(sm);

    float* ZC  = (float*)(sm + OFF_ZC);
    float* UA  = (float*)(sm + OFF_UA);
    float* DV  = (float*)(sm + OFF_DV);
    int*   RID = (int*)  (sm + OFF_RID);
    float* LG  = (float*)(sm + OFF_LG);
    float* AT  = (float*)(sm + OFF_AT);
    float* CA  = (float*)(sm + OFF_CA);
    float* CB  = (float*)(sm + OFF_CB);
    float* PART= (float*)(sm + OFF_PART);

    int tid = threadIdx.x, w = tid >> 5, lane = tid & 31;
    int b0 = blockIdx.x * 2;

    // ---- stage W2 chunk 0 early (overlaps Phase A's gmem loads) ----
    {
        const char* srcb = (const char*)g_w2;
#pragma unroll
        for (int i = 0; i < 8; ++i) {
            int g = tid + i * NT;               // 4096 granules of 16B
            int r = g >> 5, gc = g & 31;
            CP_ASYNC16(smb + OFF_B0 + r * RSTRIDE + gc * 16,
                       srcb + r * 512 + gc * 16);
        }
        CP_COMMIT();
    }

    // ---- Phase A: TransH projection -> bf16 SMEM rows; save d, rid ----
    for (int row = w; row < 128; row += 16) {
        int gb = b0 + (row >> 6);
        int n  = row & 63;
        int r  = rid_g[gb * NB + n];
        const float4* er = (const float4*)(e_g + ((size_t)gb * NB + n) * DIM);
        const float4* wp = (const float4*)(g_wn + (size_t)r * DIM);
        float4 e0 = er[2*lane], e1 = er[2*lane+1];
        float4 w0 = wp[2*lane], w1 = wp[2*lane+1];
        float d = e0.x*w0.x + e0.y*w0.y + e0.z*w0.z + e0.w*w0.w
                + e1.x*w1.x + e1.y*w1.y + e1.z*w1.z + e1.w*w1.w;
#pragma unroll
        for (int o = 16; o; o >>= 1) d += __shfl_xor_sync(~0u, d, o);
        float m = (r < CNT_E) ? 1.0f : 0.0f;
        __nv_bfloat162 p0 = __floats2bfloat162_rn((e0.x - d*w0.x)*m, (e0.y - d*w0.y)*m);
        __nv_bfloat162 p1 = __floats2bfloat162_rn((e0.z - d*w0.z)*m, (e0.w - d*w0.w)*m);
        __nv_bfloat162 p2 = __floats2bfloat162_rn((e1.x - d*w1.x)*m, (e1.y - d*w1.y)*m);
        __nv_bfloat162 p3 = __floats2bfloat162_rn((e1.z - d*w1.z)*m, (e1.w - d*w1.w)*m);
        uint4 pk;
        pk.x = *(uint32_t*)&p0; pk.y = *(uint32_t*)&p1;
        pk.z = *(uint32_t*)&p2; pk.w = *(uint32_t*)&p3;
        *(uint4*)(sm + OFF_EA + row * RSTRIDE + lane * 16) = pk;
        if (lane == 0) { DV[row] = d; RID[row] = r; }
    }
    {
        int q0 = qrid_g[b0], q1 = qrid_g[b0 + 1];
        for (int o = tid; o < HID; o += NT) {
            ZC[o]       = g_zc[(size_t)q0 * HID + o];
            ZC[512 + o] = g_zc[(size_t)q1 * HID + o];
            UA[o]       = ua_g[o];
        }
    }
    __syncthreads();

    // ---- Phase B: 4 N-chunks of 128 cols; cp.async double-buffered W2 ----
    int mw = w & 3, nw = w >> 2;               // 4 x 4 warp grid
    int m0 = mw * 32, n0 = nw * 32;

    uint32_t rowA0 = smb + OFF_EA + (m0 + (lane & 15)) * RSTRIDE + (lane >> 4) * 16;
    uint32_t rowA1 = rowA0 + 16 * RSTRIDE;
    uint32_t rbOff[2];
#pragma unroll
    for (int j = 0; j < 2; ++j)
        rbOff[j] = (uint32_t)((n0 + j * 16 + (lane & 7) + ((lane >> 4) << 3)) * RSTRIDE
                              + ((lane >> 3) & 1) * 16);

    const float* zcb = ZC + (m0 >> 6) * 512;
    float p[4] = {0.f, 0.f, 0.f, 0.f};

#pragma unroll 1
    for (int c = 0; c < 4; ++c) {
        if (c < 3) {
            const char* srcb = (const char*)g_w2 + (size_t)(c + 1) * 128 * 512;
            uint32_t dstb = smb + (((c + 1) & 1) ? OFF_B1 : OFF_B0);
#pragma unroll
            for (int i = 0; i < 8; ++i) {
                int g = tid + i * NT;
                int r = g >> 5, gc = g & 31;
                CP_ASYNC16(dstb + r * RSTRIDE + gc * 16, srcb + r * 512 + gc * 16);
            }
            CP_COMMIT();
            CP_WAIT1();
        } else {
            CP_WAIT0();
        }
        __syncthreads();

        uint32_t bBase = smb + ((c & 1) ? OFF_B1 : OFF_B0);
        float acc[2][4][4];
#pragma unroll
        for (int im = 0; im < 2; ++im)
#pragma unroll
            for (int jn = 0; jn < 4; ++jn)
#pragma unroll
                for (int e = 0; e < 4; ++e) acc[im][jn][e] = 0.f;

#pragma unroll
        for (int ks = 0; ks < 16; ++ks) {
            uint32_t kb = ks * 32;
            uint32_t a0[4], a1[4], bfr[2][4];
            LDSM4(a0, rowA0 + kb);
            LDSM4(a1, rowA1 + kb);
#pragma unroll
            for (int j = 0; j < 2; ++j) LDSM4(bfr[j], bBase + rbOff[j] + kb);
#pragma unroll
            for (int jn = 0; jn < 4; ++jn) {
                uint32_t bb0 = bfr[jn >> 1][(jn & 1) * 2];
                uint32_t bb1 = bfr[jn >> 1][(jn & 1) * 2 + 1];
                MMA16816(acc[0][jn], a0, bb0, bb1);
                MMA16816(acc[1][jn], a1, bb0, bb1);
            }
        }

        // fused epilogue: logit partial += ua * tanh(v + zc)
        int cbase = c * 128 + n0 + (lane & 3) * 2;
#pragma unroll
        for (int im = 0; im < 2; ++im)
#pragma unroll
            for (int jn = 0; jn < 4; ++jn) {
                int col0 = cbase + jn * 8;
#pragma unroll
                for (int e = 0; e < 4; ++e) {
                    int col = col0 + (e & 1);
                    float h = tanh_fast(acc[im][jn][e] + zcb[col]);
                    p[im * 2 + (e >> 1)] = fmaf(UA[col], h, p[im * 2 + (e >> 1)]);
                }
            }
        __syncthreads();
    }

    // ---- reduce partials across the 4 lanes of each row group ----
#pragma unroll
    for (int o = 1; o <= 2; o <<= 1)
#pragma unroll
        for (int k = 0; k < 4; ++k) p[k] += __shfl_xor_sync(~0u, p[k], o);
    if ((lane & 3) == 0) {
#pragma unroll
        for (int k = 0; k < 4; ++k) {
            int row = m0 + (k >> 1) * 16 + (k & 1) * 8 + (lane >> 2);
            PART[row * 4 + nw] = p[k];
        }
    }
    __syncthreads();

    if (tid < 128) {
        float s = PART[tid * 4] + PART[tid * 4 + 1] + PART[tid * 4 + 2] + PART[tid * 4 + 3];
        if (RID[tid] == CNT_E) s -= 1e19f;
        LG[tid] = s;
    }
    __syncthreads();

    // ---- softmax + rw (warp i handles batch i) ----
    if (w < 2) {
        int base = w * 64;
        float x0 = LG[base + lane], x1 = LG[base + 32 + lane];
        float mx = fmaxf(x0, x1);
#pragma unroll
        for (int o = 16; o; o >>= 1) mx = fmaxf(mx, __shfl_xor_sync(~0u, mx, o));
        float ex0 = __expf(x0 - mx), ex1 = __expf(x1 - mx);
        float s = ex0 + ex1;
#pragma unroll
        for (int o = 16; o; o >>= 1) s += __shfl_xor_sync(~0u, s, o);
        float inv = 1.0f / s;
        AT[base + lane]      = ex0 * inv + rw_g[(b0 + w) * NB + lane];
        AT[base + 32 + lane] = ex1 * inv + rw_g[(b0 + w) * NB + 32 + lane];
    }
    __syncthreads();
    if (tid < 128) {
        int r = RID[tid];
        float m = (r < CNT_E) ? 1.0f : 0.0f;
        float a = AT[tid] * m;
        CA[tid] = a;
        CB[tid] = a * DV[tid];
    }
    __syncthreads();

    // ---- Phase D: out = sum_n CA*e - CB*wn; 512 threads = 2 batches x 256 dims
    {
        int i = tid >> 8;              // batch within pair
        int d = tid & 255;             // dim
        int gb = b0 + i;
        const float* eb = e_g + (size_t)gb * NB * DIM + d;
        float acc = 0.0f;
#pragma unroll 8
        for (int n = 0; n < 64; ++n) {
            float ca = CA[i * 64 + n], cb = CB[i * 64 + n];
            acc += ca * eb[n * DIM] - cb * g_wn[(size_t)RID[i * 64 + n] * DIM + d];
        }
        out_g[(size_t)gb * DIM + d] = acc;
    }
}

// ---------------------------------------------------------------------------
extern "C" void kernel_launch(void* const* d_in, const int* in_sizes, int n_in,
                              void* d_out, int out_size) {
    const int*   rid  = (const int*)d_in[0];
    const float* e    = (const float*)d_in[1];
    const float* rw   = (const float*)d_in[2];
    const int*   qrid = (const int*)d_in[3];
    const float* wr   = (const float*)d_in[4];
    const float* zq   = (const float*)d_in[5];
    const float* W    = (const float*)d_in[6];
    const float* Wb   = (const float*)d_in[7];
    const float* ua   = (const float*)d_in[8];
    float* out = (float*)d_out;

    static bool attr_set = false;
    if (!attr_set) {
        cudaFuncSetAttribute(enc_attn_kernel,
                             cudaFuncAttributeMaxDynamicSharedMemorySize, SMEM_BYTES);
        attr_set = true;
    }

    wn_kernel<<<N_WR, 32>>>(wr);
    zc_kernel<<<N_ZQ / 4, 256>>>(W, Wb, zq);
    w2pack_kernel<<<HID, DIM>>>(W);
    enc_attn_kernel<<<B_SZ / 2, NT, SMEM_BYTES>>>(rid, e, rw, qrid, ua, out);
}

// round 7
// speedup vs baseline: 6.4523x; 1.0633x over previous
#include <cuda_runtime.h>
#include <cuda_bf16.h>
#include <cstdint>

#define B_SZ   4096
#define NB     64
#define DIM    256
#define N_WR   1001
#define N_ZQ   1000
#define CNT_E  1000
#define HID    512

// -------- device globals (scratch; allocation-free per harness rules) -------
static __device__ float g_wn[N_WR * DIM];            // normalized hyperplanes
static __device__ float g_zc[N_ZQ * HID];            // W1@zq + b
static __device__ __nv_bfloat16 g_w2[HID * DIM];     // W2 bf16 [o][k] row-major

// ---------------------------------------------------------------------------
// helpers
// ---------------------------------------------------------------------------
__device__ __forceinline__ uint32_t smem_u32(const void* p) {
    uint32_t a;
    asm("{ .reg .u64 t; cvta.to.shared.u64 t, %1; cvt.u32.u64 %0, t; }" : "=r"(a) : "l"(p));
    return a;
}
__device__ __forceinline__ float tanh_fast(float x) {
    float y; asm("tanh.approx.f32 %0, %1;" : "=f"(y) : "f"(x)); return y;
}

#define LDSM4(r, addr)                                                        \
    asm volatile("ldmatrix.sync.aligned.m8n8.x4.shared.b16 {%0,%1,%2,%3}, [%4];" \
        : "=r"((r)[0]), "=r"((r)[1]), "=r"((r)[2]), "=r"((r)[3]) : "r"(addr))

#define MMA16816(d, a, b0, b1)                                                \
    asm volatile("mma.sync.aligned.m16n8k16.row.col.f32.bf16.bf16.f32 "       \
        "{%0,%1,%2,%3}, {%4,%5,%6,%7}, {%8,%9}, {%0,%1,%2,%3};"               \
        : "+f"((d)[0]), "+f"((d)[1]), "+f"((d)[2]), "+f"((d)[3])              \
        : "r"((a)[0]), "r"((a)[1]), "r"((a)[2]), "r"((a)[3]), "r"(b0), "r"(b1))

#define CP_ASYNC16(dst, src) \
    asm volatile("cp.async.cg.shared.global [%0], [%1], 16;" :: "r"(dst), "l"(src))
#define CP_COMMIT()  asm volatile("cp.async.commit_group;" ::: "memory")
#define CP_WAIT0()   asm volatile("cp.async.wait_group 0;" ::: "memory")
#define CP_WAIT1()   asm volatile("cp.async.wait_group 1;" ::: "memory")

// ---------------------------------------------------------------------------
// Prep kernel 1: normalize w_r rows (one warp per row)
// ---------------------------------------------------------------------------
__global__ void wn_kernel(const float* __restrict__ wr) {
    int r = blockIdx.x, lane = threadIdx.x;
    const float4* row = (const float4*)(wr + r * DIM);
    float4 a = row[lane], b = row[32 + lane];
    float ss = a.x*a.x + a.y*a.y + a.z*a.z + a.w*a.w
             + b.x*b.x + b.y*b.y + b.z*b.z + b.w*b.w;
#pragma unroll
    for (int o = 16; o; o >>= 1) ss += __shfl_xor_sync(~0u, ss, o);
    float inv = 1.0f / fmaxf(sqrtf(ss), 1e-12f);
    float4* out = (float4*)(g_wn + r * DIM);
    float4 oa = {a.x*inv, a.y*inv, a.z*inv, a.w*inv};
    float4 ob = {b.x*inv, b.y*inv, b.z*inv, b.w*inv};
    out[lane] = oa; out[32 + lane] = ob;
}

// ---------------------------------------------------------------------------
// Prep kernel 2: zc[q][o] = W1[o]·zq[q] + bias[o]
// ---------------------------------------------------------------------------
__global__ void zc_kernel(const float* __restrict__ W, const float* __restrict__ bias,
                          const float* __restrict__ zq) {
    __shared__ float zs[4][DIM];
    int q0 = blockIdx.x * 4, tid = threadIdx.x;
#pragma unroll
    for (int qq = 0; qq < 4; ++qq) zs[qq][tid] = zq[(q0 + qq) * DIM + tid];
    __syncthreads();
    int warp = tid >> 5, lane = tid & 31;
    for (int o = warp; o < HID; o += 8) {
        const float4* Wr = (const float4*)(W + (size_t)o * HID);
        float4 w0 = Wr[lane], w1 = Wr[32 + lane];
        float p[4];
#pragma unroll
        for (int qq = 0; qq < 4; ++qq) {
            const float4* z4 = (const float4*)zs[qq];
            float4 z0 = z4[lane], z1 = z4[32 + lane];
            p[qq] = w0.x*z0.x + w0.y*z0.y + w0.z*z0.z + w0.w*z0.w
                  + w1.x*z1.x + w1.y*z1.y + w1.z*z1.z + w1.w*z1.w;
        }
#pragma unroll
        for (int off = 16; off; off >>= 1)
#pragma unroll
            for (int qq = 0; qq < 4; ++qq) p[qq] += __shfl_xor_sync(~0u, p[qq], off);
        if (lane == 0) {
            float bo = bias[o];
#pragma unroll
            for (int qq = 0; qq < 4; ++qq) g_zc[(q0 + qq) * HID + o] = p[qq] + bo;
        }
    }
}

// ---------------------------------------------------------------------------
// Prep kernel 3: pack W2 (cols 256..511 of attn_W_w) -> bf16 row-major [o][k]
// ---------------------------------------------------------------------------
__global__ void w2pack_kernel(const float* __restrict__ W) {
    int o = blockIdx.x, k = threadIdx.x;
    g_w2[o * DIM + k] = __float2bfloat16(W[(size_t)o * HID + DIM + k]);
}

// ---------------------------------------------------------------------------
// Main kernel: one CTA per 2 batches, 512 threads (16 warps, 4m x 4n).
// ---------------------------------------------------------------------------
#define RSTRIDE   528
#define OFF_EA    0
#define OFF_B0    67584
#define OFF_B1    135168
#define OFF_ZC    202752
#define OFF_UA    206848
#define OFF_DV    208896
#define OFF_RID   209408
#define OFF_LG    209920
#define OFF_AT    210432
#define OFF_CA    210944
#define OFF_CB    211456
#define OFF_PART  211968
#define SMEM_BYTES 214016

#define NT 512

__global__ __launch_bounds__(NT, 1)
void enc_attn_kernel(const int*   __restrict__ rid_g,
                     const float* __restrict__ e_g,
                     const float* __restrict__ rw_g,
                     const int*   __restrict__ qrid_g,
                     const float* __restrict__ ua_g,
                     float*       __restrict__ out_g) {
    extern __shared__ char sm[];
    uint32_t smb = smem_u32(sm);

    float* ZC  = (float*)(sm + OFF_ZC);
    float* UA  = (float*)(sm + OFF_UA);
    float* DV  = (float*)(sm + OFF_DV);
    int*   RID = (int*)  (sm + OFF_RID);
    float* LG  = (float*)(sm + OFF_LG);
    float* AT  = (float*)(sm + OFF_AT);
    float* CA  = (float*)(sm + OFF_CA);
    float* CB  = (float*)(sm + OFF_CB);
    float* PART= (float*)(sm + OFF_PART);

    int tid = threadIdx.x, w = tid >> 5, lane = tid & 31;
    int b0 = blockIdx.x * 2;

    // ---- stage W2 chunk 0 early (overlaps Phase A's gmem loads) ----
    {
        const char* srcb = (const char*)g_w2;
#pragma unroll
        for (int i = 0; i < 8; ++i) {
            int g = tid + i * NT;               // 4096 granules of 16B
            int r = g >> 5, gc = g & 31;
            CP_ASYNC16(smb + OFF_B0 + r * RSTRIDE + gc * 16,
                       srcb + r * 512 + gc * 16);
        }
        CP_COMMIT();
    }

    // ---- Phase A: TransH projection, 2 rows per iteration for MLP ----
#pragma unroll 1
    for (int it = 0; it < 4; ++it) {
        int rowa = w + it * 32;
        int rowb = rowa + 16;
        int ga = b0 + (rowa >> 6), na = rowa & 63;
        int gb = b0 + (rowb >> 6), nb = rowb & 63;
        int ra = rid_g[ga * NB + na];
        int rb = rid_g[gb * NB + nb];
        const float4* ea = (const float4*)(e_g + ((size_t)ga * NB + na) * DIM);
        const float4* eb = (const float4*)(e_g + ((size_t)gb * NB + nb) * DIM);
        const float4* wa = (const float4*)(g_wn + (size_t)ra * DIM);
        const float4* wb = (const float4*)(g_wn + (size_t)rb * DIM);
        float4 e0a = ea[2*lane], e1a = ea[2*lane+1];
        float4 e0b = eb[2*lane], e1b = eb[2*lane+1];
        float4 w0a = wa[2*lane], w1a = wa[2*lane+1];
        float4 w0b = wb[2*lane], w1b = wb[2*lane+1];
        float da = e0a.x*w0a.x + e0a.y*w0a.y + e0a.z*w0a.z + e0a.w*w0a.w
                 + e1a.x*w1a.x + e1a.y*w1a.y + e1a.z*w1a.z + e1a.w*w1a.w;
        float db = e0b.x*w0b.x + e0b.y*w0b.y + e0b.z*w0b.z + e0b.w*w0b.w
                 + e1b.x*w1b.x + e1b.y*w1b.y + e1b.z*w1b.z + e1b.w*w1b.w;
#pragma unroll
        for (int o = 16; o; o >>= 1) {
            da += __shfl_xor_sync(~0u, da, o);
            db += __shfl_xor_sync(~0u, db, o);
        }
        float ma = (ra < CNT_E) ? 1.0f : 0.0f;
        float mb = (rb < CNT_E) ? 1.0f : 0.0f;
        {
            __nv_bfloat162 p0 = __floats2bfloat162_rn((e0a.x - da*w0a.x)*ma, (e0a.y - da*w0a.y)*ma);
            __nv_bfloat162 p1 = __floats2bfloat162_rn((e0a.z - da*w0a.z)*ma, (e0a.w - da*w0a.w)*ma);
            __nv_bfloat162 p2 = __floats2bfloat162_rn((e1a.x - da*w1a.x)*ma, (e1a.y - da*w1a.y)*ma);
            __nv_bfloat162 p3 = __floats2bfloat162_rn((e1a.z - da*w1a.z)*ma, (e1a.w - da*w1a.w)*ma);
            uint4 pk;
            pk.x = *(uint32_t*)&p0; pk.y = *(uint32_t*)&p1;
            pk.z = *(uint32_t*)&p2; pk.w = *(uint32_t*)&p3;
            *(uint4*)(sm + OFF_EA + rowa * RSTRIDE + lane * 16) = pk;
        }
        {
            __nv_bfloat162 p0 = __floats2bfloat162_rn((e0b.x - db*w0b.x)*mb, (e0b.y - db*w0b.y)*mb);
            __nv_bfloat162 p1 = __floats2bfloat162_rn((e0b.z - db*w0b.z)*mb, (e0b.w - db*w0b.w)*mb);
            __nv_bfloat162 p2 = __floats2bfloat162_rn((e1b.x - db*w1b.x)*mb, (e1b.y - db*w1b.y)*mb);
            __nv_bfloat162 p3 = __floats2bfloat162_rn((e1b.z - db*w1b.z)*mb, (e1b.w - db*w1b.w)*mb);
            uint4 pk;
            pk.x = *(uint32_t*)&p0; pk.y = *(uint32_t*)&p1;
            pk.z = *(uint32_t*)&p2; pk.w = *(uint32_t*)&p3;
            *(uint4*)(sm + OFF_EA + rowb * RSTRIDE + lane * 16) = pk;
        }
        if (lane == 0) {
            DV[rowa] = da; RID[rowa] = ra;
            DV[rowb] = db; RID[rowb] = rb;
        }
    }
    {
        int q0 = qrid_g[b0], q1 = qrid_g[b0 + 1];
        for (int o = tid; o < HID; o += NT) {
            ZC[o]       = g_zc[(size_t)q0 * HID + o];
            ZC[512 + o] = g_zc[(size_t)q1 * HID + o];
            UA[o]       = ua_g[o];
        }
    }
    __syncthreads();

    // ---- Phase B: 4 N-chunks of 128 cols; cp.async double-buffered W2 ----
    int mw = w & 3, nw = w >> 2;               // 4 x 4 warp grid
    int m0 = mw * 32, n0 = nw * 32;

    uint32_t rowA0 = smb + OFF_EA + (m0 + (lane & 15)) * RSTRIDE + (lane >> 4) * 16;
    uint32_t rowA1 = rowA0 + 16 * RSTRIDE;
    uint32_t rbOff[2];
#pragma unroll
    for (int j = 0; j < 2; ++j)
        rbOff[j] = (uint32_t)((n0 + j * 16 + (lane & 7) + ((lane >> 4) << 3)) * RSTRIDE
                              + ((lane >> 3) & 1) * 16);

    const float* zcb = ZC + (m0 >> 6) * 512;
    float p[4] = {0.f, 0.f, 0.f, 0.f};

#pragma unroll 1
    for (int c = 0; c < 4; ++c) {
        if (c < 3) {
            const char* srcb = (const char*)g_w2 + (size_t)(c + 1) * 128 * 512;
            uint32_t dstb = smb + (((c + 1) & 1) ? OFF_B1 : OFF_B0);
#pragma unroll
            for (int i = 0; i < 8; ++i) {
                int g = tid + i * NT;
                int r = g >> 5, gc = g & 31;
                CP_ASYNC16(dstb + r * RSTRIDE + gc * 16, srcb + r * 512 + gc * 16);
            }
            CP_COMMIT();
            CP_WAIT1();
        } else {
            CP_WAIT0();
        }
        __syncthreads();

        uint32_t bBase = smb + ((c & 1) ? OFF_B1 : OFF_B0);
        float acc[2][4][4];
#pragma unroll
        for (int im = 0; im < 2; ++im)
#pragma unroll
            for (int jn = 0; jn < 4; ++jn)
#pragma unroll
                for (int e = 0; e < 4; ++e) acc[im][jn][e] = 0.f;

#pragma unroll
        for (int ks = 0; ks < 16; ++ks) {
            uint32_t kb = ks * 32;
            uint32_t a0[4], a1[4], bfr[2][4];
            LDSM4(a0, rowA0 + kb);
            LDSM4(a1, rowA1 + kb);
#pragma unroll
            for (int j = 0; j < 2; ++j) LDSM4(bfr[j], bBase + rbOff[j] + kb);
#pragma unroll
            for (int jn = 0; jn < 4; ++jn) {
                uint32_t bb0 = bfr[jn >> 1][(jn & 1) * 2];
                uint32_t bb1 = bfr[jn >> 1][(jn & 1) * 2 + 1];
                MMA16816(acc[0][jn], a0, bb0, bb1);
                MMA16816(acc[1][jn], a1, bb0, bb1);
            }
        }

        // fused epilogue: logit partial += ua * tanh(v + zc), float2 zc/ua
        int cbase = c * 128 + n0 + (lane & 3) * 2;
#pragma unroll
        for (int jn = 0; jn < 4; ++jn) {
            int col0 = cbase + jn * 8;
            float2 zc2 = *(const float2*)(zcb + col0);
            float2 ua2 = *(const float2*)(UA + col0);
#pragma unroll
            for (int im = 0; im < 2; ++im) {
                float h0 = tanh_fast(acc[im][jn][0] + zc2.x);
                float h1 = tanh_fast(acc[im][jn][1] + zc2.y);
                float h2 = tanh_fast(acc[im][jn][2] + zc2.x);
                float h3 = tanh_fast(acc[im][jn][3] + zc2.y);
                float t0 = fmaf(ua2.x, h0, fmaf(ua2.y, h1, 0.f));
                float t1 = fmaf(ua2.x, h2, fmaf(ua2.y, h3, 0.f));
                p[im * 2 + 0] += t0;
                p[im * 2 + 1] += t1;
            }
        }
        __syncthreads();
    }

    // ---- reduce partials across the 4 lanes of each row group ----
#pragma unroll
    for (int o = 1; o <= 2; o <<= 1)
#pragma unroll
        for (int k = 0; k < 4; ++k) p[k] += __shfl_xor_sync(~0u, p[k], o);
    if ((lane & 3) == 0) {
#pragma unroll
        for (int k = 0; k < 4; ++k) {
            int row = m0 + (k >> 1) * 16 + (k & 1) * 8 + (lane >> 2);
            PART[row * 4 + nw] = p[k];
        }
    }
    __syncthreads();

    if (tid < 128) {
        float s = PART[tid * 4] + PART[tid * 4 + 1] + PART[tid * 4 + 2] + PART[tid * 4 + 3];
        if (RID[tid] == CNT_E) s -= 1e19f;
        LG[tid] = s;
    }
    __syncthreads();

    // ---- softmax + rw (warp i handles batch i) ----
    if (w < 2) {
        int base = w * 64;
        float x0 = LG[base + lane], x1 = LG[base + 32 + lane];
        float mx = fmaxf(x0, x1);
#pragma unroll
        for (int o = 16; o; o >>= 1) mx = fmaxf(mx, __shfl_xor_sync(~0u, mx, o));
        float ex0 = __expf(x0 - mx), ex1 = __expf(x1 - mx);
        float s = ex0 + ex1;
#pragma unroll
        for (int o = 16; o; o >>= 1) s += __shfl_xor_sync(~0u, s, o);
        float inv = 1.0f / s;
        AT[base + lane]      = ex0 * inv + rw_g[(b0 + w) * NB + lane];
        AT[base + 32 + lane] = ex1 * inv + rw_g[(b0 + w) * NB + 32 + lane];
    }
    __syncthreads();
    if (tid < 128) {
        int r = RID[tid];
        float m = (r < CNT_E) ? 1.0f : 0.0f;
        float a = AT[tid] * m;
        CA[tid] = a;
        CB[tid] = a * DV[tid];
    }
    __syncthreads();

    // ---- Phase D: out = sum_n CA*e - CB*wn; 512 threads = 2 batches x 256 dims
    {
        int i = tid >> 8;              // batch within pair
        int d = tid & 255;             // dim
        int gb = b0 + i;
        const float* eb = e_g + (size_t)gb * NB * DIM + d;
        float acc = 0.0f;
#pragma unroll 16
        for (int n = 0; n < 64; ++n) {
            float ca = CA[i * 64 + n], cb = CB[i * 64 + n];
            acc += ca * eb[n * DIM] - cb * g_wn[(size_t)RID[i * 64 + n] * DIM + d];
        }
        out_g[(size_t)gb * DIM + d] = acc;
    }
}

// ---------------------------------------------------------------------------
extern "C" void kernel_launch(void* const* d_in, const int* in_sizes, int n_in,
                              void* d_out, int out_size) {
    const int*   rid  = (const int*)d_in[0];
    const float* e    = (const float*)d_in[1];
    const float* rw   = (const float*)d_in[2];
    const int*   qrid = (const int*)d_in[3];
    const float* wr   = (const float*)d_in[4];
    const float* zq   = (const float*)d_in[5];
    const float* W    = (const float*)d_in[6];
    const float* Wb   = (const float*)d_in[7];
    const float* ua   = (const float*)d_in[8];
    float* out = (float*)d_out;

    static bool attr_set = false;
    if (!attr_set) {
        cudaFuncSetAttribute(enc_attn_kernel,
                             cudaFuncAttributeMaxDynamicSharedMemorySize, SMEM_BYTES);
        attr_set = true;
    }

    wn_kernel<<<N_WR, 32>>>(wr);
    zc_kernel<<<N_ZQ / 4, 256>>>(W, Wb, zq);
    w2pack_kernel<<<HID, DIM>>>(W);
    enc_attn_kernel<<<B_SZ / 2, NT, SMEM_BYTES>>>(rid, e, rw, qrid, ua, out);
}

// round 9
// speedup vs baseline: 6.5496x; 1.0151x over previous
#include <cuda_runtime.h>
#include <cuda_bf16.h>
#include <cstdint>

#define B_SZ   4096
#define NB     64
#define DIM    256
#define N_WR   1001
#define N_ZQ   1000
#define CNT_E  1000
#define HID    512

// -------- device globals (scratch; allocation-free per harness rules) -------
static __device__ float g_wn[N_WR * DIM];            // normalized hyperplanes
static __device__ float g_zc[N_ZQ * HID];            // W1@zq + b
static __device__ __nv_bfloat16 g_w2[HID * DIM];     // W2 bf16 [o][k] row-major

// ---------------------------------------------------------------------------
// helpers
// ---------------------------------------------------------------------------
__device__ __forceinline__ uint32_t smem_u32(const void* p) {
    uint32_t a;
    asm("{ .reg .u64 t; cvta.to.shared.u64 t, %1; cvt.u32.u64 %0, t; }" : "=r"(a) : "l"(p));
    return a;
}
__device__ __forceinline__ float tanh_fast(float x) {
    float y; asm("tanh.approx.f32 %0, %1;" : "=f"(y) : "f"(x)); return y;
}

#define LDSM4(r, addr)                                                        \
    asm volatile("ldmatrix.sync.aligned.m8n8.x4.shared.b16 {%0,%1,%2,%3}, [%4];" \
        : "=r"((r)[0]), "=r"((r)[1]), "=r"((r)[2]), "=r"((r)[3]) : "r"(addr))

#define MMA16816(d, a, b0, b1)                                                \
    asm volatile("mma.sync.aligned.m16n8k16.row.col.f32.bf16.bf16.f32 "       \
        "{%0,%1,%2,%3}, {%4,%5,%6,%7}, {%8,%9}, {%0,%1,%2,%3};"               \
        : "+f"((d)[0]), "+f"((d)[1]), "+f"((d)[2]), "+f"((d)[3])              \
        : "r"((a)[0]), "r"((a)[1]), "r"((a)[2]), "r"((a)[3]), "r"(b0), "r"(b1))

#define CP_ASYNC16(dst, src) \
    asm volatile("cp.async.cg.shared.global [%0], [%1], 16;" :: "r"(dst), "l"(src))
#define CP_COMMIT()  asm volatile("cp.async.commit_group;" ::: "memory")
#define CP_WAIT0()   asm volatile("cp.async.wait_group 0;" ::: "memory")

// ---------------------------------------------------------------------------
// Prep kernel 1: normalize w_r rows (one warp per row)
// ---------------------------------------------------------------------------
__global__ void wn_kernel(const float* __restrict__ wr) {
    int r = blockIdx.x, lane = threadIdx.x;
    const float4* row = (const float4*)(wr + r * DIM);
    float4 a = row[lane], b = row[32 + lane];
    float ss = a.x*a.x + a.y*a.y + a.z*a.z + a.w*a.w
             + b.x*b.x + b.y*b.y + b.z*b.z + b.w*b.w;
#pragma unroll
    for (int o = 16; o; o >>= 1) ss += __shfl_xor_sync(~0u, ss, o);
    float inv = 1.0f / fmaxf(sqrtf(ss), 1e-12f);
    float4* out = (float4*)(g_wn + r * DIM);
    float4 oa = {a.x*inv, a.y*inv, a.z*inv, a.w*inv};
    float4 ob = {b.x*inv, b.y*inv, b.z*inv, b.w*inv};
    out[lane] = oa; out[32 + lane] = ob;
}

// ---------------------------------------------------------------------------
// Prep kernel 2: zc[q][o] = W1[o]·zq[q] + bias[o]
// ---------------------------------------------------------------------------
__global__ void zc_kernel(const float* __restrict__ W, const float* __restrict__ bias,
                          const float* __restrict__ zq) {
    __shared__ float zs[4][DIM];
    int q0 = blockIdx.x * 4, tid = threadIdx.x;
#pragma unroll
    for (int qq = 0; qq < 4; ++qq) zs[qq][tid] = zq[(q0 + qq) * DIM + tid];
    __syncthreads();
    int warp = tid >> 5, lane = tid & 31;
    for (int o = warp; o < HID; o += 8) {
        const float4* Wr = (const float4*)(W + (size_t)o * HID);
        float4 w0 = Wr[lane], w1 = Wr[32 + lane];
        float p[4];
#pragma unroll
        for (int qq = 0; qq < 4; ++qq) {
            const float4* z4 = (const float4*)zs[qq];
            float4 z0 = z4[lane], z1 = z4[32 + lane];
            p[qq] = w0.x*z0.x + w0.y*z0.y + w0.z*z0.z + w0.w*z0.w
                  + w1.x*z1.x + w1.y*z1.y + w1.z*z1.z + w1.w*z1.w;
        }
#pragma unroll
        for (int off = 16; off; off >>= 1)
#pragma unroll
            for (int qq = 0; qq < 4; ++qq) p[qq] += __shfl_xor_sync(~0u, p[qq], off);
        if (lane == 0) {
            float bo = bias[o];
#pragma unroll
            for (int qq = 0; qq < 4; ++qq) g_zc[(q0 + qq) * HID + o] = p[qq] + bo;
        }
    }
}

// ---------------------------------------------------------------------------
// Prep kernel 3: pack W2 (cols 256..511 of attn_W_w) -> bf16 row-major [o][k]
// ---------------------------------------------------------------------------
__global__ void w2pack_kernel(const float* __restrict__ W) {
    int o = blockIdx.x, k = threadIdx.x;
    g_w2[o * DIM + k] = __float2bfloat16(W[(size_t)o * HID + DIM + k]);
}

// ---------------------------------------------------------------------------
// Main kernel: ONE batch per CTA, 256 threads (8 warps, 2m x 4n warp grid),
// ~105.5 KB SMEM -> 2 CTAs/SM. Single B buffer; sibling CTA hides fill latency.
// SMEM (bytes):
//   EA   [64 rows][264 bf16] (stride 528B)   0      .. 33792
//   B0   [128][264 bf16]                     33792  .. 101376
//   ZC 101376 (512 f)   UA 103424 (512 f)
//   DV 105472  RID 105728  LG 105984  AT 106240  CA 106496  CB 106752
//   PART [64][4] f32 107008 .. 108032
// ---------------------------------------------------------------------------
#define RSTRIDE   528
#define OFF_EA    0
#define OFF_B0    33792
#define OFF_ZC    101376
#define OFF_UA    103424
#define OFF_DV    105472
#define OFF_RID   105728
#define OFF_LG    105984
#define OFF_AT    106240
#define OFF_CA    106496
#define OFF_CB    106752
#define OFF_PART  107008
#define SMEM_BYTES 108032

#define NT 256

__global__ __launch_bounds__(NT, 2)
void enc_attn_kernel(const int*   __restrict__ rid_g,
                     const float* __restrict__ e_g,
                     const float* __restrict__ rw_g,
                     const int*   __restrict__ qrid_g,
                     const float* __restrict__ ua_g,
                     float*       __restrict__ out_g) {
    extern __shared__ char sm[];
    uint32_t smb = smem_u32(sm);

    float* ZC  = (float*)(sm + OFF_ZC);
    float* UA  = (float*)(sm + OFF_UA);
    float* DV  = (float*)(sm + OFF_DV);
    int*   RID = (int*)  (sm + OFF_RID);
    float* LG  = (float*)(sm + OFF_LG);
    float* AT  = (float*)(sm + OFF_AT);
    float* CA  = (float*)(sm + OFF_CA);
    float* CB  = (float*)(sm + OFF_CB);
    float* PART= (float*)(sm + OFF_PART);

    int tid = threadIdx.x, w = tid >> 5, lane = tid & 31;
    int b = blockIdx.x;

    // ---- stage W2 chunk 0 early (overlaps Phase A's gmem loads) ----
    {
        const char* srcb = (const char*)g_w2;
#pragma unroll
        for (int i = 0; i < 16; ++i) {
            int g = tid + i * NT;               // 4096 granules of 16B
            int r = g >> 5, gc = g & 31;
            CP_ASYNC16(smb + OFF_B0 + r * RSTRIDE + gc * 16,
                       srcb + r * 512 + gc * 16);
        }
        CP_COMMIT();
    }

    // ---- Phase A: TransH projection, 2 rows per iteration for MLP ----
#pragma unroll 1
    for (int it = 0; it < 4; ++it) {
        int rowa = w + it * 16;
        int rowb = rowa + 8;
        int ra = rid_g[b * NB + rowa];
        int rb = rid_g[b * NB + rowb];
        const float4* ea = (const float4*)(e_g + ((size_t)b * NB + rowa) * DIM);
        const float4* eb = (const float4*)(e_g + ((size_t)b * NB + rowb) * DIM);
        const float4* wa = (const float4*)(g_wn + (size_t)ra * DIM);
        const float4* wb = (const float4*)(g_wn + (size_t)rb * DIM);
        float4 e0a = ea[2*lane], e1a = ea[2*lane+1];
        float4 e0b = eb[2*lane], e1b = eb[2*lane+1];
        float4 w0a = wa[2*lane], w1a = wa[2*lane+1];
        float4 w0b = wb[2*lane], w1b = wb[2*lane+1];
        float da = e0a.x*w0a.x + e0a.y*w0a.y + e0a.z*w0a.z + e0a.w*w0a.w
                 + e1a.x*w1a.x + e1a.y*w1a.y + e1a.z*w1a.z + e1a.w*w1a.w;
        float db = e0b.x*w0b.x + e0b.y*w0b.y + e0b.z*w0b.z + e0b.w*w0b.w
                 + e1b.x*w1b.x + e1b.y*w1b.y + e1b.z*w1b.z + e1b.w*w1b.w;
#pragma unroll
        for (int o = 16; o; o >>= 1) {
            da += __shfl_xor_sync(~0u, da, o);
            db += __shfl_xor_sync(~0u, db, o);
        }
        float ma = (ra < CNT_E) ? 1.0f : 0.0f;
        float mb = (rb < CNT_E) ? 1.0f : 0.0f;
        {
            __nv_bfloat162 p0 = __floats2bfloat162_rn((e0a.x - da*w0a.x)*ma, (e0a.y - da*w0a.y)*ma);
            __nv_bfloat162 p1 = __floats2bfloat162_rn((e0a.z - da*w0a.z)*ma, (e0a.w - da*w0a.w)*ma);
            __nv_bfloat162 p2 = __floats2bfloat162_rn((e1a.x - da*w1a.x)*ma, (e1a.y - da*w1a.y)*ma);
            __nv_bfloat162 p3 = __floats2bfloat162_rn((e1a.z - da*w1a.z)*ma, (e1a.w - da*w1a.w)*ma);
            uint4 pk;
            pk.x = *(uint32_t*)&p0; pk.y = *(uint32_t*)&p1;
            pk.z = *(uint32_t*)&p2; pk.w = *(uint32_t*)&p3;
            *(uint4*)(sm + OFF_EA + rowa * RSTRIDE + lane * 16) = pk;
        }
        {
            __nv_bfloat162 p0 = __floats2bfloat162_rn((e0b.x - db*w0b.x)*mb, (e0b.y - db*w0b.y)*mb);
            __nv_bfloat162 p1 = __floats2bfloat162_rn((e0b.z - db*w0b.z)*mb, (e0b.w - db*w0b.w)*mb);
            __nv_bfloat162 p2 = __floats2bfloat162_rn((e1b.x - db*w1b.x)*mb, (e1b.y - db*w1b.y)*mb);
            __nv_bfloat162 p3 = __floats2bfloat162_rn((e1b.z - db*w1b.z)*mb, (e1b.w - db*w1b.w)*mb);
            uint4 pk;
            pk.x = *(uint32_t*)&p0; pk.y = *(uint32_t*)&p1;
            pk.z = *(uint32_t*)&p2; pk.w = *(uint32_t*)&p3;
            *(uint4*)(sm + OFF_EA + rowb * RSTRIDE + lane * 16) = pk;
        }
        if (lane == 0) {
            DV[rowa] = da; RID[rowa] = ra;
            DV[rowb] = db; RID[rowb] = rb;
        }
    }
    {
        int q = qrid_g[b];
        for (int o = tid; o < HID; o += NT) {
            ZC[o] = g_zc[(size_t)q * HID + o];
            UA[o] = ua_g[o];
        }
    }
    __syncthreads();

    // ---- Phase B: 4 N-chunks of 128 cols; single B buffer ----
    int mw = w & 1, nw = w >> 1;               // 2m x 4n warp grid
    int m0 = mw * 32, n0 = nw * 32;

    uint32_t rowA0 = smb + OFF_EA + (m0 + (lane & 15)) * RSTRIDE + (lane >> 4) * 16;
    uint32_t rowA1 = rowA0 + 16 * RSTRIDE;
    uint32_t rbOff[2];
#pragma unroll
    for (int j = 0; j < 2; ++j)
        rbOff[j] = (uint32_t)((n0 + j * 16 + (lane & 7) + ((lane >> 4) << 3)) * RSTRIDE
                              + ((lane >> 3) & 1) * 16);

    float p[4] = {0.f, 0.f, 0.f, 0.f};
    uint32_t bBase = smb + OFF_B0;

#pragma unroll 1
    for (int c = 0; c < 4; ++c) {
        if (c > 0) {   // refill the single buffer (previous reads done at loop-end sync)
            const char* srcb = (const char*)g_w2 + (size_t)c * 128 * 512;
#pragma unroll
            for (int i = 0; i < 16; ++i) {
                int g = tid + i * NT;
                int r = g >> 5, gc = g & 31;
                CP_ASYNC16(smb + OFF_B0 + r * RSTRIDE + gc * 16, srcb + r * 512 + gc * 16);
            }
            CP_COMMIT();
        }
        CP_WAIT0();
        __syncthreads();

        float acc[2][4][4];
#pragma unroll
        for (int im = 0; im < 2; ++im)
#pragma unroll
            for (int jn = 0; jn < 4; ++jn)
#pragma unroll
                for (int e = 0; e < 4; ++e) acc[im][jn][e] = 0.f;

#pragma unroll
        for (int ks = 0; ks < 16; ++ks) {
            uint32_t kb = ks * 32;
            uint32_t a0[4], a1[4], bfr[2][4];
            LDSM4(a0, rowA0 + kb);
            LDSM4(a1, rowA1 + kb);
#pragma unroll
            for (int j = 0; j < 2; ++j) LDSM4(bfr[j], bBase + rbOff[j] + kb);
#pragma unroll
            for (int jn = 0; jn < 4; ++jn) {
                uint32_t bb0 = bfr[jn >> 1][(jn & 1) * 2];
                uint32_t bb1 = bfr[jn >> 1][(jn & 1) * 2 + 1];
                MMA16816(acc[0][jn], a0, bb0, bb1);
                MMA16816(acc[1][jn], a1, bb0, bb1);
            }
        }

        // fused epilogue: logit partial += ua * tanh(v + zc), float2 zc/ua
        int cbase = c * 128 + n0 + (lane & 3) * 2;
#pragma unroll
        for (int jn = 0; jn < 4; ++jn) {
            int col0 = cbase + jn * 8;
            float2 zc2 = *(const float2*)(ZC + col0);
            float2 ua2 = *(const float2*)(UA + col0);
#pragma unroll
            for (int im = 0; im < 2; ++im) {
                float h0 = tanh_fast(acc[im][jn][0] + zc2.x);
                float h1 = tanh_fast(acc[im][jn][1] + zc2.y);
                float h2 = tanh_fast(acc[im][jn][2] + zc2.x);
                float h3 = tanh_fast(acc[im][jn][3] + zc2.y);
                float t0 = fmaf(ua2.x, h0, fmaf(ua2.y, h1, 0.f));
                float t1 = fmaf(ua2.x, h2, fmaf(ua2.y, h3, 0.f));
                p[im * 2 + 0] += t0;
                p[im * 2 + 1] += t1;
            }
        }
        __syncthreads();                        // reads done before next refill
    }

    // ---- reduce partials across the 4 lanes of each row group ----
#pragma unroll
    for (int o = 1; o <= 2; o <<= 1)
#pragma unroll
        for (int k = 0; k < 4; ++k) p[k] += __shfl_xor_sync(~0u, p[k], o);
    if ((lane & 3) == 0) {
#pragma unroll
        for (int k = 0; k < 4; ++k) {
            int row = m0 + (k >> 1) * 16 + (k & 1) * 8 + (lane >> 2);
            PART[row * 4 + nw] = p[k];
        }
    }
    __syncthreads();

    if (tid < 64) {
        float s = PART[tid * 4] + PART[tid * 4 + 1] + PART[tid * 4 + 2] + PART[tid * 4 + 3];
        if (RID[tid] == CNT_E) s -= 1e19f;
        LG[tid] = s;
    }
    __syncthreads();

    // ---- softmax + rw (warp 0) ----
    if (tid < 32) {
        float x0 = LG[lane], x1 = LG[32 + lane];
        float mx = fmaxf(x0, x1);
#pragma unroll
        for (int o = 16; o; o >>= 1) mx = fmaxf(mx, __shfl_xor_sync(~0u, mx, o));
        float ex0 = __expf(x0 - mx), ex1 = __expf(x1 - mx);
        float s = ex0 + ex1;
#pragma unroll
        for (int o = 16; o; o >>= 1) s += __shfl_xor_sync(~0u, s, o);
        float inv = 1.0f / s;
        AT[lane]      = ex0 * inv + rw_g[b * NB + lane];
        AT[32 + lane] = ex1 * inv + rw_g[b * NB + 32 + lane];
    }
    __syncthreads();
    if (tid < 64) {
        int r = RID[tid];
        float m = (r < CNT_E) ? 1.0f : 0.0f;
        float a = AT[tid] * m;
        CA[tid] = a;
        CB[tid] = a * DV[tid];
    }
    __syncthreads();

    // ---- Phase D: out[d] = sum_n CA*e - CB*wn  (256 threads = 256 dims) ----
    {
        const float* eb = e_g + (size_t)b * NB * DIM + tid;
        float acc = 0.0f;
#pragma unroll 16
        for (int n = 0; n < 64; ++n) {
            float ca = CA[n], cb = CB[n];
            acc += ca * eb[n * DIM] - cb * g_wn[(size_t)RID[n] * DIM + tid];
        }
        out_g[(size_t)b * DIM + tid] = acc;
    }
}

// ---------------------------------------------------------------------------
extern "C" void kernel_launch(void* const* d_in, const int* in_sizes, int n_in,
                              void* d_out, int out_size) {
    const int*   rid  = (const int*)d_in[0];
    const float* e    = (const float*)d_in[1];
    const float* rw   = (const float*)d_in[2];
    const int*   qrid = (const int*)d_in[3];
    const float* wr   = (const float*)d_in[4];
    const float* zq   = (const float*)d_in[5];
    const float* W    = (const float*)d_in[6];
    const float* Wb   = (const float*)d_in[7];
    const float* ua   = (const float*)d_in[8];
    float* out = (float*)d_out;

    static bool attr_set = false;
    if (!attr_set) {
        cudaFuncSetAttribute(enc_attn_kernel,
                             cudaFuncAttributeMaxDynamicSharedMemorySize, SMEM_BYTES);
        attr_set = true;
    }

    wn_kernel<<<N_WR, 32>>>(wr);
    zc_kernel<<<N_ZQ / 4, 256>>>(W, Wb, zq);
    w2pack_kernel<<<HID, DIM>>>(W);
    enc_attn_kernel<<<B_SZ, NT, SMEM_BYTES>>>(rid, e, rw, qrid, ua, out);
}

// round 10
// speedup vs baseline: 6.7079x; 1.0242x over previous
#include <cuda_runtime.h>
#include <cuda_bf16.h>
#include <cstdint>

#define B_SZ   4096
#define NB     64
#define DIM    256
#define N_WR   1001
#define N_ZQ   1000
#define CNT_E  1000
#define HID    512

// -------- device globals (scratch; allocation-free per harness rules) -------
static __device__ float g_wn[N_WR * DIM];            // normalized hyperplanes
static __device__ float g_zc[N_ZQ * HID];            // W1@zq + b
static __device__ __nv_bfloat16 g_w2[HID * DIM];     // W2 bf16 [o][k] row-major

// ---------------------------------------------------------------------------
// helpers
// ---------------------------------------------------------------------------
__device__ __forceinline__ uint32_t smem_u32(const void* p) {
    uint32_t a;
    asm("{ .reg .u64 t; cvta.to.shared.u64 t, %1; cvt.u32.u64 %0, t; }" : "=r"(a) : "l"(p));
    return a;
}
__device__ __forceinline__ float tanh_fast(float x) {
    float y; asm("tanh.approx.f32 %0, %1;" : "=f"(y) : "f"(x)); return y;
}

#define LDSM4(r, addr)                                                        \
    asm volatile("ldmatrix.sync.aligned.m8n8.x4.shared.b16 {%0,%1,%2,%3}, [%4];" \
        : "=r"((r)[0]), "=r"((r)[1]), "=r"((r)[2]), "=r"((r)[3]) : "r"(addr))

#define MMA16816(d, a, b0, b1)                                                \
    asm volatile("mma.sync.aligned.m16n8k16.row.col.f32.bf16.bf16.f32 "       \
        "{%0,%1,%2,%3}, {%4,%5,%6,%7}, {%8,%9}, {%0,%1,%2,%3};"               \
        : "+f"((d)[0]), "+f"((d)[1]), "+f"((d)[2]), "+f"((d)[3])              \
        : "r"((a)[0]), "r"((a)[1]), "r"((a)[2]), "r"((a)[3]), "r"(b0), "r"(b1))

#define CP_ASYNC16(dst, src) \
    asm volatile("cp.async.cg.shared.global [%0], [%1], 16;" :: "r"(dst), "l"(src))
#define CP_COMMIT()  asm volatile("cp.async.commit_group;" ::: "memory")
#define CP_WAIT0()   asm volatile("cp.async.wait_group 0;" ::: "memory")
#define CP_WAIT1()   asm volatile("cp.async.wait_group 1;" ::: "memory")

// ---------------------------------------------------------------------------
// Prep kernel 1: normalize w_r rows (one warp per row)
// ---------------------------------------------------------------------------
__global__ void wn_kernel(const float* __restrict__ wr) {
    int r = blockIdx.x, lane = threadIdx.x;
    const float4* row = (const float4*)(wr + r * DIM);
    float4 a = row[lane], b = row[32 + lane];
    float ss = a.x*a.x + a.y*a.y + a.z*a.z + a.w*a.w
             + b.x*b.x + b.y*b.y + b.z*b.z + b.w*b.w;
#pragma unroll
    for (int o = 16; o; o >>= 1) ss += __shfl_xor_sync(~0u, ss, o);
    float inv = 1.0f / fmaxf(sqrtf(ss), 1e-12f);
    float4* out = (float4*)(g_wn + r * DIM);
    float4 oa = {a.x*inv, a.y*inv, a.z*inv, a.w*inv};
    float4 ob = {b.x*inv, b.y*inv, b.z*inv, b.w*inv};
    out[lane] = oa; out[32 + lane] = ob;
}

// ---------------------------------------------------------------------------
// Prep kernel 2: zc[q][o] = W1[o]·zq[q] + bias[o]
// ---------------------------------------------------------------------------
__global__ void zc_kernel(const float* __restrict__ W, const float* __restrict__ bias,
                          const float* __restrict__ zq) {
    __shared__ float zs[4][DIM];
    int q0 = blockIdx.x * 4, tid = threadIdx.x;
#pragma unroll
    for (int qq = 0; qq < 4; ++qq) zs[qq][tid] = zq[(q0 + qq) * DIM + tid];
    __syncthreads();
    int warp = tid >> 5, lane = tid & 31;
    for (int o = warp; o < HID; o += 8) {
        const float4* Wr = (const float4*)(W + (size_t)o * HID);
        float4 w0 = Wr[lane], w1 = Wr[32 + lane];
        float p[4];
#pragma unroll
        for (int qq = 0; qq < 4; ++qq) {
            const float4* z4 = (const float4*)zs[qq];
            float4 z0 = z4[lane], z1 = z4[32 + lane];
            p[qq] = w0.x*z0.x + w0.y*z0.y + w0.z*z0.z + w0.w*z0.w
                  + w1.x*z1.x + w1.y*z1.y + w1.z*z1.z + w1.w*z1.w;
        }
#pragma unroll
        for (int off = 16; off; off >>= 1)
#pragma unroll
            for (int qq = 0; qq < 4; ++qq) p[qq] += __shfl_xor_sync(~0u, p[qq], off);
        if (lane == 0) {
            float bo = bias[o];
#pragma unroll
            for (int qq = 0; qq < 4; ++qq) g_zc[(q0 + qq) * HID + o] = p[qq] + bo;
        }
    }
}

// ---------------------------------------------------------------------------
// Prep kernel 3: pack W2 (cols 256..511 of attn_W_w) -> bf16 row-major [o][k]
// ---------------------------------------------------------------------------
__global__ void w2pack_kernel(const float* __restrict__ W) {
    int o = blockIdx.x, k = threadIdx.x;
    g_w2[o * DIM + k] = __float2bfloat16(W[(size_t)o * HID + DIM + k]);
}

// ---------------------------------------------------------------------------
// Main kernel: ONE batch per CTA, 256 threads (8 warps, 2m x 4n warp grid),
// ~105.5 KB SMEM -> 2 CTAs/SM. Single B buffer with HALF-K software pipelining:
// ks0-7 read row bytes [0,256) (K1), ks8-15 read [256,512) (K2); each half is
// refilled with the NEXT chunk's data while the other half computes.
// ---------------------------------------------------------------------------
#define RSTRIDE   528
#define OFF_EA    0
#define OFF_B0    33792
#define OFF_ZC    101376
#define OFF_UA    103424
#define OFF_DV    105472
#define OFF_RID   105728
#define OFF_LG    105984
#define OFF_AT    106240
#define OFF_CA    106496
#define OFF_CB    106752
#define OFF_PART  107008
#define SMEM_BYTES 108032

#define NT 256

// fill one K-half (256 B per row, 128 rows) of the B buffer from W2 chunk
__device__ __forceinline__ void fill_half(uint32_t smb, const char* w2chunk,
                                          int half, int tid) {
    const char* srcb = w2chunk + half * 256;
    uint32_t dstb = smb + OFF_B0 + half * 256;
#pragma unroll
    for (int i = 0; i < 8; ++i) {
        int g = tid + i * NT;           // 2048 granules of 16B
        int r = g >> 4, gc = g & 15;    // 16 granules per row-half
        CP_ASYNC16(dstb + r * RSTRIDE + gc * 16, srcb + r * 512 + gc * 16);
    }
    CP_COMMIT();
}

__global__ __launch_bounds__(NT, 2)
void enc_attn_kernel(const int*   __restrict__ rid_g,
                     const float* __restrict__ e_g,
                     const float* __restrict__ rw_g,
                     const int*   __restrict__ qrid_g,
                     const float* __restrict__ ua_g,
                     float*       __restrict__ out_g) {
    extern __shared__ char sm[];
    uint32_t smb = smem_u32(sm);

    float* ZC  = (float*)(sm + OFF_ZC);
    float* UA  = (float*)(sm + OFF_UA);
    float* DV  = (float*)(sm + OFF_DV);
    int*   RID = (int*)  (sm + OFF_RID);
    float* LG  = (float*)(sm + OFF_LG);
    float* AT  = (float*)(sm + OFF_AT);
    float* CA  = (float*)(sm + OFF_CA);
    float* CB  = (float*)(sm + OFF_CB);
    float* PART= (float*)(sm + OFF_PART);

    int tid = threadIdx.x, w = tid >> 5, lane = tid & 31;
    int b = blockIdx.x;

    // ---- prologue: stage chunk 0 as two half-fills (2 commit groups) ----
    fill_half(smb, (const char*)g_w2, 0, tid);
    fill_half(smb, (const char*)g_w2, 1, tid);

    // ---- Phase A: TransH projection; rids upfront, 2 groups of 4 batched rows
    {
        int rid8[8];
#pragma unroll
        for (int k = 0; k < 8; ++k) rid8[k] = rid_g[b * NB + w + k * 8];

#pragma unroll
        for (int gp = 0; gp < 2; ++gp) {
            float4 ev[4][2], wv[4][2];
#pragma unroll
            for (int k = 0; k < 4; ++k) {
                int row = w + (gp * 4 + k) * 8;
                const float4* ea = (const float4*)(e_g + ((size_t)b * NB + row) * DIM);
                ev[k][0] = ea[2 * lane]; ev[k][1] = ea[2 * lane + 1];
            }
#pragma unroll
            for (int k = 0; k < 4; ++k) {
                const float4* wa = (const float4*)(g_wn + (size_t)rid8[gp * 4 + k] * DIM);
                wv[k][0] = wa[2 * lane]; wv[k][1] = wa[2 * lane + 1];
            }
            float d[4];
#pragma unroll
            for (int k = 0; k < 4; ++k) {
                d[k] = ev[k][0].x*wv[k][0].x + ev[k][0].y*wv[k][0].y
                     + ev[k][0].z*wv[k][0].z + ev[k][0].w*wv[k][0].w
                     + ev[k][1].x*wv[k][1].x + ev[k][1].y*wv[k][1].y
                     + ev[k][1].z*wv[k][1].z + ev[k][1].w*wv[k][1].w;
            }
#pragma unroll
            for (int o = 16; o; o >>= 1)
#pragma unroll
                for (int k = 0; k < 4; ++k) d[k] += __shfl_xor_sync(~0u, d[k], o);
#pragma unroll
            for (int k = 0; k < 4; ++k) {
                int row = w + (gp * 4 + k) * 8;
                int r = rid8[gp * 4 + k];
                float m = (r < CNT_E) ? 1.0f : 0.0f;
                float dk = d[k];
                __nv_bfloat162 p0 = __floats2bfloat162_rn((ev[k][0].x - dk*wv[k][0].x)*m,
                                                          (ev[k][0].y - dk*wv[k][0].y)*m);
                __nv_bfloat162 p1 = __floats2bfloat162_rn((ev[k][0].z - dk*wv[k][0].z)*m,
                                                          (ev[k][0].w - dk*wv[k][0].w)*m);
                __nv_bfloat162 p2 = __floats2bfloat162_rn((ev[k][1].x - dk*wv[k][1].x)*m,
                                                          (ev[k][1].y - dk*wv[k][1].y)*m);
                __nv_bfloat162 p3 = __floats2bfloat162_rn((ev[k][1].z - dk*wv[k][1].z)*m,
                                                          (ev[k][1].w - dk*wv[k][1].w)*m);
                uint4 pk;
                pk.x = *(uint32_t*)&p0; pk.y = *(uint32_t*)&p1;
                pk.z = *(uint32_t*)&p2; pk.w = *(uint32_t*)&p3;
                *(uint4*)(sm + OFF_EA + row * RSTRIDE + lane * 16) = pk;
                if (lane == 0) { DV[row] = dk; RID[row] = r; }
            }
        }
    }
    {
        int q = qrid_g[b];
        for (int o = tid; o < HID; o += NT) {
            ZC[o] = g_zc[(size_t)q * HID + o];
            UA[o] = ua_g[o];
        }
    }
    __syncthreads();

    // ---- Phase B: 4 N-chunks of 128 cols; half-K pipelined single buffer ----
    int mw = w & 1, nw = w >> 1;               // 2m x 4n warp grid
    int m0 = mw * 32, n0 = nw * 32;

    uint32_t rowA0 = smb + OFF_EA + (m0 + (lane & 15)) * RSTRIDE + (lane >> 4) * 16;
    uint32_t rowA1 = rowA0 + 16 * RSTRIDE;
    uint32_t rbOff[2];
#pragma unroll
    for (int j = 0; j < 2; ++j)
        rbOff[j] = (uint32_t)((n0 + j * 16 + (lane & 7) + ((lane >> 4) << 3)) * RSTRIDE
                              + ((lane >> 3) & 1) * 16);

    float p[4] = {0.f, 0.f, 0.f, 0.f};
    uint32_t bBase = smb + OFF_B0;

#pragma unroll 1
    for (int c = 0; c < 4; ++c) {
        // K1(c) ready (most-recent pending group is K2(c) or the prologue's)
        CP_WAIT1();
        __syncthreads();

        float acc[2][4][4];
#pragma unroll
        for (int im = 0; im < 2; ++im)
#pragma unroll
            for (int jn = 0; jn < 4; ++jn)
#pragma unroll
                for (int e = 0; e < 4; ++e) acc[im][jn][e] = 0.f;

        // ---- first half: ks 0..7 (K1 bytes [0,256)) ----
#pragma unroll
        for (int ks = 0; ks < 8; ++ks) {
            uint32_t kb = ks * 32;
            uint32_t a0[4], a1[4], bfr[2][4];
            LDSM4(a0, rowA0 + kb);
            LDSM4(a1, rowA1 + kb);
#pragma unroll
            for (int j = 0; j < 2; ++j) LDSM4(bfr[j], bBase + rbOff[j] + kb);
#pragma unroll
            for (int jn = 0; jn < 4; ++jn) {
                uint32_t bb0 = bfr[jn >> 1][(jn & 1) * 2];
                uint32_t bb1 = bfr[jn >> 1][(jn & 1) * 2 + 1];
                MMA16816(acc[0][jn], a0, bb0, bb1);
                MMA16816(acc[1][jn], a1, bb0, bb1);
            }
        }
        __syncthreads();                         // K1(c) reads done
        if (c < 3) {
            fill_half(smb, (const char*)g_w2 + (size_t)(c + 1) * 65536, 0, tid);
            CP_WAIT1();                          // K2(c) ready (K1(c+1) pending)
        } else {
            CP_WAIT0();                          // K2(3) ready
        }
        __syncthreads();

        // ---- second half: ks 8..15 (K2 bytes [256,512)) ----
#pragma unroll
        for (int ks = 8; ks < 16; ++ks) {
            uint32_t kb = ks * 32;
            uint32_t a0[4], a1[4], bfr[2][4];
            LDSM4(a0, rowA0 + kb);
            LDSM4(a1, rowA1 + kb);
#pragma unroll
            for (int j = 0; j < 2; ++j) LDSM4(bfr[j], bBase + rbOff[j] + kb);
#pragma unroll
            for (int jn = 0; jn < 4; ++jn) {
                uint32_t bb0 = bfr[jn >> 1][(jn & 1) * 2];
                uint32_t bb1 = bfr[jn >> 1][(jn & 1) * 2 + 1];
                MMA16816(acc[0][jn], a0, bb0, bb1);
                MMA16816(acc[1][jn], a1, bb0, bb1);
            }
        }
        __syncthreads();                         // K2(c) reads done
        if (c < 3)
            fill_half(smb, (const char*)g_w2 + (size_t)(c + 1) * 65536, 1, tid);

        // fused epilogue (registers + ZC/UA LDS only; overlaps the K2 fill)
        int cbase = c * 128 + n0 + (lane & 3) * 2;
#pragma unroll
        for (int jn = 0; jn < 4; ++jn) {
            int col0 = cbase + jn * 8;
            float2 zc2 = *(const float2*)(ZC + col0);
            float2 ua2 = *(const float2*)(UA + col0);
#pragma unroll
            for (int im = 0; im < 2; ++im) {
                float h0 = tanh_fast(acc[im][jn][0] + zc2.x);
                float h1 = tanh_fast(acc[im][jn][1] + zc2.y);
                float h2 = tanh_fast(acc[im][jn][2] + zc2.x);
                float h3 = tanh_fast(acc[im][jn][3] + zc2.y);
                float t0 = fmaf(ua2.x, h0, fmaf(ua2.y, h1, 0.f));
                float t1 = fmaf(ua2.x, h2, fmaf(ua2.y, h3, 0.f));
                p[im * 2 + 0] += t0;
                p[im * 2 + 1] += t1;
            }
        }
    }

    // ---- reduce partials across the 4 lanes of each row group ----
#pragma unroll
    for (int o = 1; o <= 2; o <<= 1)
#pragma unroll
        for (int k = 0; k < 4; ++k) p[k] += __shfl_xor_sync(~0u, p[k], o);
    if ((lane & 3) == 0) {
#pragma unroll
        for (int k = 0; k < 4; ++k) {
            int row = m0 + (k >> 1) * 16 + (k & 1) * 8 + (lane >> 2);
            PART[row * 4 + nw] = p[k];
        }
    }
    __syncthreads();

    if (tid < 64) {
        float s = PART[tid * 4] + PART[tid * 4 + 1] + PART[tid * 4 + 2] + PART[tid * 4 + 3];
        if (RID[tid] == CNT_E) s -= 1e19f;
        LG[tid] = s;
    }
    __syncthreads();

    // ---- softmax + rw (warp 0) ----
    if (tid < 32) {
        float x0 = LG[lane], x1 = LG[32 + lane];
        float mx = fmaxf(x0, x1);
#pragma unroll
        for (int o = 16; o; o >>= 1) mx = fmaxf(mx, __shfl_xor_sync(~0u, mx, o));
        float ex0 = __expf(x0 - mx), ex1 = __expf(x1 - mx);
        float s = ex0 + ex1;
#pragma unroll
        for (int o = 16; o; o >>= 1) s += __shfl_xor_sync(~0u, s, o);
        float inv = 1.0f / s;
        AT[lane]      = ex0 * inv + rw_g[b * NB + lane];
        AT[32 + lane] = ex1 * inv + rw_g[b * NB + 32 + lane];
    }
    __syncthreads();
    if (tid < 64) {
        int r = RID[tid];
        float m = (r < CNT_E) ? 1.0f : 0.0f;
        float a = AT[tid] * m;
        CA[tid] = a;
        CB[tid] = a * DV[tid];
    }
    __syncthreads();

    // ---- Phase D: out[d] = sum_n CA*e - CB*wn  (256 threads = 256 dims) ----
    {
        const float* eb = e_g + (size_t)b * NB * DIM + tid;
        float acc = 0.0f;
#pragma unroll 16
        for (int n = 0; n < 64; ++n) {
            float ca = CA[n], cb = CB[n];
            acc += ca * eb[n * DIM] - cb * g_wn[(size_t)RID[n] * DIM + tid];
        }
        out_g[(size_t)b * DIM + tid] = acc;
    }
}

// ---------------------------------------------------------------------------
extern "C" void kernel_launch(void* const* d_in, const int* in_sizes, int n_in,
                              void* d_out, int out_size) {
    const int*   rid  = (const int*)d_in[0];
    const float* e    = (const float*)d_in[1];
    const float* rw   = (const float*)d_in[2];
    const int*   qrid = (const int*)d_in[3];
    const float* wr   = (const float*)d_in[4];
    const float* zq   = (const float*)d_in[5];
    const float* W    = (const float*)d_in[6];
    const float* Wb   = (const float*)d_in[7];
    const float* ua   = (const float*)d_in[8];
    float* out = (float*)d_out;

    static bool attr_set = false;
    if (!attr_set) {
        cudaFuncSetAttribute(enc_attn_kernel,
                             cudaFuncAttributeMaxDynamicSharedMemorySize, SMEM_BYTES);
        attr_set = true;
    }

    wn_kernel<<<N_WR, 32>>>(wr);
    zc_kernel<<<N_ZQ / 4, 256>>>(W, Wb, zq);
    w2pack_kernel<<<HID, DIM>>>(W);
    enc_attn_kernel<<<B_SZ, NT, SMEM_BYTES>>>(rid, e, rw, qrid, ua, out);
}

// round 14
// speedup vs baseline: 7.3200x; 1.0913x over previous
#include <cuda_runtime.h>
#include <cuda_bf16.h>
#include <cstdint>

#define B_SZ   4096
#define NB     64
#define DIM    256
#define N_WR   1001
#define N_ZQ   1000
#define CNT_E  1000
#define HID    512

// -------- device globals (scratch; allocation-free per harness rules) -------
static __device__ float g_wn[N_WR * DIM];            // normalized hyperplanes
static __device__ float g_zc[N_ZQ * HID];            // W1@zq + b
static __device__ uint32_t g_w2f[65536];             // W2 bf16 pre-packed in MMA
                                                     // B-fragment order (256 KB)

// ---------------------------------------------------------------------------
// helpers
// ---------------------------------------------------------------------------
__device__ __forceinline__ uint32_t smem_u32(const void* p) {
    uint32_t a;
    asm("{ .reg .u64 t; cvta.to.shared.u64 t, %1; cvt.u32.u64 %0, t; }" : "=r"(a) : "l"(p));
    return a;
}
__device__ __forceinline__ float tanh_fast(float x) {
    float y; asm("tanh.approx.f32 %0, %1;" : "=f"(y) : "f"(x)); return y;
}

#define LDSM4(r, addr)                                                        \
    asm volatile("ldmatrix.sync.aligned.m8n8.x4.shared.b16 {%0,%1,%2,%3}, [%4];" \
        : "=r"((r)[0]), "=r"((r)[1]), "=r"((r)[2]), "=r"((r)[3]) : "r"(addr))

#define MMA16816(d, a, b0, b1)                                                \
    asm volatile("mma.sync.aligned.m16n8k16.row.col.f32.bf16.bf16.f32 "       \
        "{%0,%1,%2,%3}, {%4,%5,%6,%7}, {%8,%9}, {%0,%1,%2,%3};"               \
        : "+f"((d)[0]), "+f"((d)[1]), "+f"((d)[2]), "+f"((d)[3])              \
        : "r"((a)[0]), "r"((a)[1]), "r"((a)[2]), "r"((a)[3]), "r"(b0), "r"(b1))

// ---------------------------------------------------------------------------
// Prep kernel 1: normalize w_r rows (one warp per row)
// ---------------------------------------------------------------------------
__global__ void wn_kernel(const float* __restrict__ wr) {
    int r = blockIdx.x, lane = threadIdx.x;
    const float4* row = (const float4*)(wr + r * DIM);
    float4 a = row[lane], b = row[32 + lane];
    float ss = a.x*a.x + a.y*a.y + a.z*a.z + a.w*a.w
             + b.x*b.x + b.y*b.y + b.z*b.z + b.w*b.w;
#pragma unroll
    for (int o = 16; o; o >>= 1) ss += __shfl_xor_sync(~0u, ss, o);
    float inv = 1.0f / fmaxf(sqrtf(ss), 1e-12f);
    float4* out = (float4*)(g_wn + r * DIM);
    float4 oa = {a.x*inv, a.y*inv, a.z*inv, a.w*inv};
    float4 ob = {b.x*inv, b.y*inv, b.z*inv, b.w*inv};
    out[lane] = oa; out[32 + lane] = ob;
}

// ---------------------------------------------------------------------------
// Prep kernel 2: zc[q][o] = W1[o]·zq[q] + bias[o]
// ---------------------------------------------------------------------------
__global__ void zc_kernel(const float* __restrict__ W, const float* __restrict__ bias,
                          const float* __restrict__ zq) {
    __shared__ float zs[4][DIM];
    int q0 = blockIdx.x * 4, tid = threadIdx.x;
#pragma unroll
    for (int qq = 0; qq < 4; ++qq) zs[qq][tid] = zq[(q0 + qq) * DIM + tid];
    __syncthreads();
    int warp = tid >> 5, lane = tid & 31;
    for (int o = warp; o < HID; o += 8) {
        const float4* Wr = (const float4*)(W + (size_t)o * HID);
        float4 w0 = Wr[lane], w1 = Wr[32 + lane];
        float p[4];
#pragma unroll
        for (int qq = 0; qq < 4; ++qq) {
            const float4* z4 = (const float4*)zs[qq];
            float4 z0 = z4[lane], z1 = z4[32 + lane];
            p[qq] = w0.x*z0.x + w0.y*z0.y + w0.z*z0.z + w0.w*z0.w
                  + w1.x*z1.x + w1.y*z1.y + w1.z*z1.z + w1.w*z1.w;
        }
#pragma unroll
        for (int off = 16; off; off >>= 1)
#pragma unroll
            for (int qq = 0; qq < 4; ++qq) p[qq] += __shfl_xor_sync(~0u, p[qq], off);
        if (lane == 0) {
            float bo = bias[o];
#pragma unroll
            for (int qq = 0; qq < 4; ++qq) g_zc[(q0 + qq) * HID + o] = p[qq] + bo;
        }
    }
}

// ---------------------------------------------------------------------------
// Prep kernel 3: pack W2 (cols 256..511 of attn_W_w) into MMA B-fragment order.
// Layout: g_w2f[ blk*256 + t*8 + r ] with blk = (c*4 + nw)*16 + ks,
//   t = lane, r = jn*2 + half; value = bf16x2( W2[n][k], W2[n][k+1] ),
//   n = (c*4+nw)*32 + jn*8 + t/4,  k = ks*16 + half*8 + 2*(t&3).
// Matches mma.m16n8k16 col-major B fragment semantics exactly.
// ---------------------------------------------------------------------------
__global__ void w2frag_kernel(const float* __restrict__ W) {
    int blk = blockIdx.x;            // 0..255
    int ks  = blk & 15;
    int nwc = blk >> 4;              // c*4 + nw, 0..15
    int tid = threadIdx.x;           // 0..255
    int t = tid >> 3, r = tid & 7;
    int n = nwc * 32 + (r >> 1) * 8 + (t >> 2);
    int k = ks * 16 + (r & 1) * 8 + (t & 3) * 2;
    float v0 = W[(size_t)n * HID + DIM + k];
    float v1 = W[(size_t)n * HID + DIM + k + 1];
    __nv_bfloat162 pk = __floats2bfloat162_rn(v0, v1);
    g_w2f[blk * 256 + t * 8 + r] = *(uint32_t*)&pk;
}

// ---------------------------------------------------------------------------
// Main kernel: ONE batch per CTA, 256 threads (8 warps, 2m x 4n warp grid).
// B operand comes straight from L2 via LDG.128 in fragment order — no SMEM
// staging, no barriers anywhere in Phase B. ~41 KB SMEM -> 2 CTAs/SM.
// ---------------------------------------------------------------------------
#define RSTRIDE   528
#define OFF_EA    0
#define OFF_ZC    33792
#define OFF_UA    35840
#define OFF_DV    37888
#define OFF_RID   38144
#define OFF_LG    38400
#define OFF_AT    38656
#define OFF_CA    38912
#define OFF_CB    39168
#define OFF_PART  39424
#define SMEM_BYTES 40448

#define NT 256

__global__ __launch_bounds__(NT, 2)
void enc_attn_kernel(const int*   __restrict__ rid_g,
                     const float* __restrict__ e_g,
                     const float* __restrict__ rw_g,
                     const int*   __restrict__ qrid_g,
                     const float* __restrict__ ua_g,
                     float*       __restrict__ out_g) {
    extern __shared__ char sm[];
    uint32_t smb = smem_u32(sm);

    float* ZC  = (float*)(sm + OFF_ZC);
    float* UA  = (float*)(sm + OFF_UA);
    float* DV  = (float*)(sm + OFF_DV);
    int*   RID = (int*)  (sm + OFF_RID);
    float* LG  = (float*)(sm + OFF_LG);
    float* AT  = (float*)(sm + OFF_AT);
    float* CA  = (float*)(sm + OFF_CA);
    float* CB  = (float*)(sm + OFF_CB);
    float* PART= (float*)(sm + OFF_PART);

    int tid = threadIdx.x, w = tid >> 5, lane = tid & 31;
    int b = blockIdx.x;

    // ---- Phase A: TransH projection; rids upfront, 2 groups of 4 batched rows
    {
        int rid8[8];
#pragma unroll
        for (int k = 0; k < 8; ++k) rid8[k] = rid_g[b * NB + w + k * 8];

#pragma unroll
        for (int gp = 0; gp < 2; ++gp) {
            float4 ev[4][2], wv[4][2];
#pragma unroll
            for (int k = 0; k < 4; ++k) {
                int row = w + (gp * 4 + k) * 8;
                const float4* ea = (const float4*)(e_g + ((size_t)b * NB + row) * DIM);
                ev[k][0] = ea[2 * lane]; ev[k][1] = ea[2 * lane + 1];
            }
#pragma unroll
            for (int k = 0; k < 4; ++k) {
                const float4* wa = (const float4*)(g_wn + (size_t)rid8[gp * 4 + k] * DIM);
                wv[k][0] = wa[2 * lane]; wv[k][1] = wa[2 * lane + 1];
            }
            float d[4];
#pragma unroll
            for (int k = 0; k < 4; ++k) {
                d[k] = ev[k][0].x*wv[k][0].x + ev[k][0].y*wv[k][0].y
                     + ev[k][0].z*wv[k][0].z + ev[k][0].w*wv[k][0].w
                     + ev[k][1].x*wv[k][1].x + ev[k][1].y*wv[k][1].y
                     + ev[k][1].z*wv[k][1].z + ev[k][1].w*wv[k][1].w;
            }
#pragma unroll
            for (int o = 16; o; o >>= 1)
#pragma unroll
                for (int k = 0; k < 4; ++k) d[k] += __shfl_xor_sync(~0u, d[k], o);
#pragma unroll
            for (int k = 0; k < 4; ++k) {
                int row = w + (gp * 4 + k) * 8;
                int r = rid8[gp * 4 + k];
                float m = (r < CNT_E) ? 1.0f : 0.0f;
                float dk = d[k];
                __nv_bfloat162 p0 = __floats2bfloat162_rn((ev[k][0].x - dk*wv[k][0].x)*m,
                                                          (ev[k][0].y - dk*wv[k][0].y)*m);
                __nv_bfloat162 p1 = __floats2bfloat162_rn((ev[k][0].z - dk*wv[k][0].z)*m,
                                                          (ev[k][0].w - dk*wv[k][0].w)*m);
                __nv_bfloat162 p2 = __floats2bfloat162_rn((ev[k][1].x - dk*wv[k][1].x)*m,
                                                          (ev[k][1].y - dk*wv[k][1].y)*m);
                __nv_bfloat162 p3 = __floats2bfloat162_rn((ev[k][1].z - dk*wv[k][1].z)*m,
                                                          (ev[k][1].w - dk*wv[k][1].w)*m);
                uint4 pk;
                pk.x = *(uint32_t*)&p0; pk.y = *(uint32_t*)&p1;
                pk.z = *(uint32_t*)&p2; pk.w = *(uint32_t*)&p3;
                *(uint4*)(sm + OFF_EA + row * RSTRIDE + lane * 16) = pk;
                if (lane == 0) { DV[row] = dk; RID[row] = r; }
            }
        }
    }
    {
        int q = qrid_g[b];
        for (int o = tid; o < HID; o += NT) {
            ZC[o] = g_zc[(size_t)q * HID + o];
            UA[o] = ua_g[o];
        }
    }
    __syncthreads();          // EA/ZC/UA visible; the ONLY barrier before Phase B ends

    // ---- Phase B: 4 N-chunk register passes; B fragments via LDG from L2 ----
    int mw = w & 1, nw = w >> 1;               // 2m x 4n warp grid
    int m0 = mw * 32, n0 = nw * 32;

    uint32_t rowA0 = smb + OFF_EA + (m0 + (lane & 15)) * RSTRIDE + (lane >> 4) * 16;
    uint32_t rowA1 = rowA0 + 16 * RSTRIDE;

    float p[4] = {0.f, 0.f, 0.f, 0.f};

#pragma unroll 1
    for (int c = 0; c < 4; ++c) {
        // fragment stream for (chunk c, warp-col nw): 64 uint4 per ks
        const uint4* bp = (const uint4*)g_w2f + ((size_t)(c * 4 + nw) * 16) * 64 + lane * 2;

        float acc[2][4][4];
#pragma unroll
        for (int im = 0; im < 2; ++im)
#pragma unroll
            for (int jn = 0; jn < 4; ++jn)
#pragma unroll
                for (int e = 0; e < 4; ++e) acc[im][jn][e] = 0.f;

#pragma unroll
        for (int ks = 0; ks < 16; ++ks) {
            uint4 bA = __ldg(bp + ks * 64);
            uint4 bB = __ldg(bp + ks * 64 + 1);
            uint32_t kb = ks * 32;
            uint32_t a0[4], a1[4];
            LDSM4(a0, rowA0 + kb);
            LDSM4(a1, rowA1 + kb);
            MMA16816(acc[0][0], a0, bA.x, bA.y);
            MMA16816(acc[0][1], a0, bA.z, bA.w);
            MMA16816(acc[0][2], a0, bB.x, bB.y);
            MMA16816(acc[0][3], a0, bB.z, bB.w);
            MMA16816(acc[1][0], a1, bA.x, bA.y);
            MMA16816(acc[1][1], a1, bA.z, bA.w);
            MMA16816(acc[1][2], a1, bB.x, bB.y);
            MMA16816(acc[1][3], a1, bB.z, bB.w);
        }

        // fused epilogue: logit partial += ua * tanh(v + zc), float2 zc/ua
        int cbase = c * 128 + n0 + (lane & 3) * 2;
#pragma unroll
        for (int jn = 0; jn < 4; ++jn) {
            int col0 = cbase + jn * 8;
            float2 zc2 = *(const float2*)(ZC + col0);
            float2 ua2 = *(const float2*)(UA + col0);
#pragma unroll
            for (int im = 0; im < 2; ++im) {
                float h0 = tanh_fast(acc[im][jn][0] + zc2.x);
                float h1 = tanh_fast(acc[im][jn][1] + zc2.y);
                float h2 = tanh_fast(acc[im][jn][2] + zc2.x);
                float h3 = tanh_fast(acc[im][jn][3] + zc2.y);
                float t0 = fmaf(ua2.x, h0, fmaf(ua2.y, h1, 0.f));
                float t1 = fmaf(ua2.x, h2, fmaf(ua2.y, h3, 0.f));
                p[im * 2 + 0] += t0;
                p[im * 2 + 1] += t1;
            }
        }
    }

    // ---- reduce partials across the 4 lanes of each row group ----
#pragma unroll
    for (int o = 1; o <= 2; o <<= 1)
#pragma unroll
        for (int k = 0; k < 4; ++k) p[k] += __shfl_xor_sync(~0u, p[k], o);
    if ((lane & 3) == 0) {
#pragma unroll
        for (int k = 0; k < 4; ++k) {
            int row = m0 + (k >> 1) * 16 + (k & 1) * 8 + (lane >> 2);
            PART[row * 4 + nw] = p[k];
        }
    }
    __syncthreads();

    if (tid < 64) {
        float s = PART[tid * 4] + PART[tid * 4 + 1] + PART[tid * 4 + 2] + PART[tid * 4 + 3];
        if (RID[tid] == CNT_E) s -= 1e19f;
        LG[tid] = s;
    }
    __syncthreads();

    // ---- softmax + rw (warp 0) ----
    if (tid < 32) {
        float x0 = LG[lane], x1 = LG[32 + lane];
        float mx = fmaxf(x0, x1);
#pragma unroll
        for (int o = 16; o; o >>= 1) mx = fmaxf(mx, __shfl_xor_sync(~0u, mx, o));
        float ex0 = __expf(x0 - mx), ex1 = __expf(x1 - mx);
        float s = ex0 + ex1;
#pragma unroll
        for (int o = 16; o; o >>= 1) s += __shfl_xor_sync(~0u, s, o);
        float inv = 1.0f / s;
        AT[lane]      = ex0 * inv + rw_g[b * NB + lane];
        AT[32 + lane] = ex1 * inv + rw_g[b * NB + 32 + lane];
    }
    __syncthreads();
    if (tid < 64) {
        int r = RID[tid];
        float m = (r < CNT_E) ? 1.0f : 0.0f;
        float a = AT[tid] * m;
        CA[tid] = a;
        CB[tid] = a * DV[tid];
    }
    __syncthreads();

    // ---- Phase D: out[d] = sum_n CA*e - CB*wn  (256 threads = 256 dims) ----
    {
        const float* eb = e_g + (size_t)b * NB * DIM + tid;
        float acc = 0.0f;
#pragma unroll 16
        for (int n = 0; n < 64; ++n) {
            float ca = CA[n], cb = CB[n];
            acc += ca * eb[n * DIM] - cb * g_wn[(size_t)RID[n] * DIM + tid];
        }
        out_g[(size_t)b * DIM + tid] = acc;
    }
}

// ---------------------------------------------------------------------------
extern "C" void kernel_launch(void* const* d_in, const int* in_sizes, int n_in,
                              void* d_out, int out_size) {
    const int*   rid  = (const int*)d_in[0];
    const float* e    = (const float*)d_in[1];
    const float* rw   = (const float*)d_in[2];
    const int*   qrid = (const int*)d_in[3];
    const float* wr   = (const float*)d_in[4];
    const float* zq   = (const float*)d_in[5];
    const float* W    = (const float*)d_in[6];
    const float* Wb   = (const float*)d_in[7];
    const float* ua   = (const float*)d_in[8];
    float* out = (float*)d_out;

    static bool attr_set = false;
    if (!attr_set) {
        cudaFuncSetAttribute(enc_attn_kernel,
                             cudaFuncAttributeMaxDynamicSharedMemorySize, SMEM_BYTES);
        attr_set = true;
    }

    wn_kernel<<<N_WR, 32>>>(wr);
    zc_kernel<<<N_ZQ / 4, 256>>>(W, Wb, zq);
    w2frag_kernel<<<256, 256>>>(W);
    enc_attn_kernel<<<B_SZ, NT, SMEM_BYTES>>>(rid, e, rw, qrid, ua, out);
}